// round 2
// baseline (speedup 1.0000x reference)
#include <cuda_runtime.h>
#include <cstdint>

#define NN 100000
#define NE 1600000
#define FH 128
#define FO 64
#define NMASK_WORDS 400000   // NN*FH/32

__device__ int      g_deg[NN];
__device__ float    g_dinv[NN];
__device__ float    g_h1[(size_t)NN * FH];
__device__ float    g_agg[(size_t)NN * FH];
__device__ float    g_h2[(size_t)NN * FO];
__device__ unsigned g_mask[NMASK_WORDS];

// ---------------- degree / norm ----------------
__global__ void k_deg_init() {
    int i = blockIdx.x * blockDim.x + threadIdx.x;
    if (i < NN) g_deg[i] = 1;   // self loop
}
__global__ void k_deg_count(const int* __restrict__ dst) {
    int e = blockIdx.x * blockDim.x + threadIdx.x;
    if (e < NE) atomicAdd(&g_deg[dst[e]], 1);
}
__global__ void k_dinv() {
    int i = blockIdx.x * blockDim.x + threadIdx.x;
    if (i < NN) g_dinv[i] = rsqrtf((float)g_deg[i]);
}

// ---------------- JAX threefry2x32 dropout mask (partitionable path) ----------------
// key(42) -> (k1,k2) = (0,42). For element i: counter = (hi,lo) of uint64 i = (0, i),
// bits[i] = out.x ^ out.y, keep <=> bit31(bits)==0  (uniform<0.5).
__device__ __forceinline__ uint2 threefry2x32_0_42(unsigned x0, unsigned x1) {
    const unsigned ks0 = 0u, ks1 = 42u, ks2 = 0u ^ 42u ^ 0x1BD11BDAu;
    x0 += ks0; x1 += ks1;
#define TF_R(r) { x0 += x1; x1 = __funnelshift_l(x1, x1, (r)); x1 ^= x0; }
    TF_R(13) TF_R(15) TF_R(26) TF_R(6)
    x0 += ks1; x1 += ks2 + 1u;
    TF_R(17) TF_R(29) TF_R(16) TF_R(24)
    x0 += ks2; x1 += ks0 + 2u;
    TF_R(13) TF_R(15) TF_R(26) TF_R(6)
    x0 += ks0; x1 += ks1 + 3u;
    TF_R(17) TF_R(29) TF_R(16) TF_R(24)
    x0 += ks1; x1 += ks2 + 4u;
    TF_R(13) TF_R(15) TF_R(26) TF_R(6)
    x0 += ks2; x1 += ks0 + 5u;
#undef TF_R
    return make_uint2(x0, x1);
}

__global__ void __launch_bounds__(256) k_mask() {
    unsigned p = blockIdx.x * 256u + threadIdx.x;   // grid is exactly NN*FH threads
    uint2 o = threefry2x32_0_42(0u, p);
    unsigned bits = o.x ^ o.y;
    unsigned m = __ballot_sync(0xffffffffu, (int)bits >= 0);  // bit31==0 -> keep
    if ((threadIdx.x & 31) == 0) g_mask[p >> 5] = m;
}

// ---------------- fp32 GEMM, K=128 fixed, 128 rows x BN cols per block ----------------
template <int BN, int TN>
__device__ __forceinline__ void gemm_body(const float* __restrict__ A,
                                          const float* __restrict__ W,
                                          float* __restrict__ C) {
    __shared__ float As[16][128];
    __shared__ float Ws[16][BN];
    const int tid = threadIdx.x;
    const int tx = tid & 15;
    const int ty = tid >> 4;
    const int row0 = blockIdx.x * 128;

    float acc[8][TN];
#pragma unroll
    for (int i = 0; i < 8; i++)
#pragma unroll
        for (int j = 0; j < TN; j++) acc[i][j] = 0.f;

    const int ar = tid >> 1;
    const int ak = (tid & 1) * 8;
    const int grow = row0 + ar;
    const bool av = (grow < NN);
    const float* Arow = A + (size_t)(av ? grow : 0) * 128;

    for (int k0 = 0; k0 < 128; k0 += 16) {
        float4 a0 = make_float4(0.f, 0.f, 0.f, 0.f), a1 = a0;
        if (av) {
            a0 = *(const float4*)(Arow + k0 + ak);
            a1 = *(const float4*)(Arow + k0 + ak + 4);
        }
        As[ak + 0][ar] = a0.x; As[ak + 1][ar] = a0.y;
        As[ak + 2][ar] = a0.z; As[ak + 3][ar] = a0.w;
        As[ak + 4][ar] = a1.x; As[ak + 5][ar] = a1.y;
        As[ak + 6][ar] = a1.z; As[ak + 7][ar] = a1.w;
        constexpr int W4 = BN / 4;
#pragma unroll
        for (int it = 0; it < (16 * W4) / 256; it++) {
            int idx = tid + it * 256;
            int kk = idx / W4, c4 = idx % W4;
            *(float4*)&Ws[kk][c4 * 4] = *(const float4*)(W + (size_t)(k0 + kk) * BN + c4 * 4);
        }
        __syncthreads();
#pragma unroll
        for (int kk = 0; kk < 16; kk++) {
            float4 av0 = *(const float4*)&As[kk][ty * 8];
            float4 av1 = *(const float4*)&As[kk][ty * 8 + 4];
            float a[8] = {av0.x, av0.y, av0.z, av0.w, av1.x, av1.y, av1.z, av1.w};
            float b[TN];
#pragma unroll
            for (int j = 0; j < TN; j += 4) {
                float4 bv = *(const float4*)&Ws[kk][tx * TN + j];
                b[j] = bv.x; b[j + 1] = bv.y; b[j + 2] = bv.z; b[j + 3] = bv.w;
            }
#pragma unroll
            for (int i = 0; i < 8; i++)
#pragma unroll
                for (int j = 0; j < TN; j++) acc[i][j] = fmaf(a[i], b[j], acc[i][j]);
        }
        __syncthreads();
    }
#pragma unroll
    for (int i = 0; i < 8; i++) {
        int r = row0 + ty * 8 + i;
        if (r < NN) {
#pragma unroll
            for (int j = 0; j < TN; j += 4) {
                *(float4*)(C + (size_t)r * BN + tx * TN + j) =
                    make_float4(acc[i][j], acc[i][j + 1], acc[i][j + 2], acc[i][j + 3]);
            }
        }
    }
}

__global__ void __launch_bounds__(256) k_gemm1(const float* __restrict__ A,
                                               const float* __restrict__ W) {
    gemm_body<128, 8>(A, W, g_h1);
}
__global__ void __launch_bounds__(256) k_gemm2(const float* __restrict__ W) {
    gemm_body<64, 4>(g_agg, W, g_h2);
}

// ---------------- aggregation ----------------
__device__ __forceinline__ void red_add_v4(float* p, float a, float b, float c, float d) {
    asm volatile("red.global.add.v4.f32 [%0], {%1, %2, %3, %4};"
                 :: "l"(p), "f"(a), "f"(b), "f"(c), "f"(d)
                 : "memory");
}

// agg1 = h1 * dinv^2   (self-loop term)
__global__ void k_init_agg1() {
    int t = blockIdx.x * blockDim.x + threadIdx.x;   // NN*32 float4 groups
    if (t >= NN * 32) return;
    int n = t >> 5;
    float s = g_dinv[n]; s = s * s;
    float4 h = *(const float4*)(g_h1 + (size_t)t * 4);
    *(float4*)(g_agg + (size_t)t * 4) = make_float4(h.x * s, h.y * s, h.z * s, h.w * s);
}

// one warp per edge, 128 floats
__global__ void __launch_bounds__(256) k_scatter128(const int* __restrict__ src,
                                                    const int* __restrict__ dst) {
    int w = (blockIdx.x * 256 + threadIdx.x) >> 5;
    if (w >= NE) return;
    int lane = threadIdx.x & 31;
    int s = __ldg(src + w), d = __ldg(dst + w);
    float nw = g_dinv[s] * g_dinv[d];
    float4 h = *(const float4*)(g_h1 + (size_t)s * 128 + lane * 4);
    red_add_v4(g_agg + (size_t)d * 128 + lane * 4, h.x * nw, h.y * nw, h.z * nw, h.w * nw);
}

// y1 = relu(agg1 + b1) * mask * 2   (in place)
__global__ void k_post1(const float* __restrict__ b1) {
    int t = blockIdx.x * blockDim.x + threadIdx.x;   // NN*32 float4 groups
    if (t >= NN * 32) return;
    int idx = t * 4;
    int f = idx & 127;
    unsigned m = g_mask[idx >> 5];
    int bit = idx & 31;
    float4 v = *(const float4*)(g_agg + (size_t)idx);
    v.x = fmaxf(v.x + b1[f + 0], 0.f) * (((m >> (bit + 0)) & 1u) ? 2.f : 0.f);
    v.y = fmaxf(v.y + b1[f + 1], 0.f) * (((m >> (bit + 1)) & 1u) ? 2.f : 0.f);
    v.z = fmaxf(v.z + b1[f + 2], 0.f) * (((m >> (bit + 2)) & 1u) ? 2.f : 0.f);
    v.w = fmaxf(v.w + b1[f + 3], 0.f) * (((m >> (bit + 3)) & 1u) ? 2.f : 0.f);
    *(float4*)(g_agg + (size_t)idx) = v;
}

// out = h2 * dinv^2 + b2
__global__ void k_init_out(const float* __restrict__ b2, float* __restrict__ out) {
    int t = blockIdx.x * blockDim.x + threadIdx.x;   // NN*16 float4 groups
    if (t >= NN * 16) return;
    int n = t >> 4;
    float s = g_dinv[n]; s = s * s;
    int idx = t * 4;
    int f = idx & 63;
    float4 h = *(const float4*)(g_h2 + (size_t)idx);
    *(float4*)(out + (size_t)idx) = make_float4(
        h.x * s + b2[f + 0], h.y * s + b2[f + 1],
        h.z * s + b2[f + 2], h.w * s + b2[f + 3]);
}

// half warp per edge, 64 floats
__global__ void __launch_bounds__(256) k_scatter64(const int* __restrict__ src,
                                                   const int* __restrict__ dst,
                                                   float* __restrict__ out) {
    int t = blockIdx.x * 256 + threadIdx.x;
    int e = t >> 4;
    if (e >= NE) return;
    int l = t & 15;
    int s = __ldg(src + e), d = __ldg(dst + e);
    float nw = g_dinv[s] * g_dinv[d];
    float4 h = *(const float4*)(g_h2 + (size_t)s * 64 + l * 4);
    red_add_v4(out + (size_t)d * 64 + l * 4, h.x * nw, h.y * nw, h.z * nw, h.w * nw);
}

// ---------------- launch ----------------
extern "C" void kernel_launch(void* const* d_in, const int* in_sizes, int n_in,
                              void* d_out, int out_size) {
    const float* x  = (const float*)d_in[0];
    const int*   ei = (const int*)d_in[1];
    const float* W1 = (const float*)d_in[2];
    const float* b1 = (const float*)d_in[3];
    const float* W2 = (const float*)d_in[4];
    const float* b2 = (const float*)d_in[5];
    const int* src = ei;
    const int* dst = ei + NE;
    float* out = (float*)d_out;

    k_deg_init<<<(NN + 255) / 256, 256>>>();
    k_deg_count<<<(NE + 255) / 256, 256>>>(dst);
    k_dinv<<<(NN + 255) / 256, 256>>>();

    k_mask<<<(NN * FH) / 256, 256>>>();

    k_gemm1<<<(NN + 127) / 128, 256>>>(x, W1);
    k_init_agg1<<<(NN * 32 + 255) / 256, 256>>>();
    k_scatter128<<<(NE * 32) / 256, 256>>>(src, dst);
    k_post1<<<(NN * 32 + 255) / 256, 256>>>(b1);

    k_gemm2<<<(NN + 127) / 128, 256>>>(W2);
    k_init_out<<<(NN * 16 + 255) / 256, 256>>>(b2, out);
    k_scatter64<<<(NE * 16) / 256, 256>>>(src, dst, out);
}

// round 3
// speedup vs baseline: 1.6459x; 1.6459x over previous
#include <cuda_runtime.h>
#include <cstdint>

#define NN 100000
#define NE 1600000
#define FH 128
#define FO 64
#define NMASK_WORDS 400000   // NN*FH/32
#define NBLK 391             // ceil(NN/256)

__device__ int      g_dege[NN];      // real in-degree (no self loop)
__device__ float    g_dinv[NN];
__device__ int      g_off[NN + 1];
__device__ int      g_cur[NN];
__device__ int      g_srcs[NE];
__device__ int      g_bsum[NBLK];
__device__ int      g_boff[NBLK];
__device__ float    g_h1[(size_t)NN * FH];
__device__ float    g_agg[(size_t)NN * FH];
__device__ float    g_h2[(size_t)NN * FO];
__device__ unsigned g_mask[NMASK_WORDS];

// ---------------- degree ----------------
__global__ void k_deg_zero() {
    int i = blockIdx.x * blockDim.x + threadIdx.x;
    if (i < NN) g_dege[i] = 0;
}
__global__ void k_deg_count(const int* __restrict__ dst) {
    int e = blockIdx.x * blockDim.x + threadIdx.x;
    if (e < NE) atomicAdd(&g_dege[dst[e]], 1);
}

// ---------------- CSR build: two-level exclusive scan ----------------
__global__ void __launch_bounds__(256) k_blocksum() {
    __shared__ int sh[8];
    int i = blockIdx.x * 256 + threadIdx.x;
    int v = (i < NN) ? g_dege[i] : 0;
#pragma unroll
    for (int o = 16; o > 0; o >>= 1) v += __shfl_down_sync(0xffffffffu, v, o);
    if ((threadIdx.x & 31) == 0) sh[threadIdx.x >> 5] = v;
    __syncthreads();
    if (threadIdx.x < 8) {
        int t = sh[threadIdx.x];
#pragma unroll
        for (int o = 4; o > 0; o >>= 1) t += __shfl_down_sync(0xffu, t, o);
        if (threadIdx.x == 0) g_bsum[blockIdx.x] = t;
    }
}

__global__ void __launch_bounds__(512) k_scan_bsum() {
    __shared__ int sh[512];
    int t = threadIdx.x;
    sh[t] = (t < NBLK) ? g_bsum[t] : 0;
    __syncthreads();
#pragma unroll
    for (int o = 1; o < 512; o <<= 1) {
        int v = (t >= o) ? sh[t - o] : 0;
        __syncthreads();
        sh[t] += v;
        __syncthreads();
    }
    if (t < NBLK) g_boff[t] = sh[t] - g_bsum[t];   // exclusive
}

__global__ void __launch_bounds__(256) k_nodeoff() {
    __shared__ int sh[256];
    int i = blockIdx.x * 256 + threadIdx.x;
    int t = threadIdx.x;
    int d = (i < NN) ? g_dege[i] : 0;
    sh[t] = d;
    __syncthreads();
#pragma unroll
    for (int o = 1; o < 256; o <<= 1) {
        int v = (t >= o) ? sh[t - o] : 0;
        __syncthreads();
        sh[t] += v;
        __syncthreads();
    }
    if (i < NN) {
        int off = g_boff[blockIdx.x] + sh[t] - d;   // exclusive
        g_off[i] = off;
        g_cur[i] = off;
        g_dinv[i] = rsqrtf((float)(d + 1));         // +1 self loop
        if (i == NN - 1) g_off[NN] = off + d;
    }
}

__global__ void k_fill(const int* __restrict__ src, const int* __restrict__ dst) {
    int e = blockIdx.x * blockDim.x + threadIdx.x;
    if (e >= NE) return;
    int slot = atomicAdd(&g_cur[dst[e]], 1);
    g_srcs[slot] = src[e];
}

// ---------------- JAX threefry2x32 dropout mask (partitionable path) ----------------
__device__ __forceinline__ uint2 threefry2x32_0_42(unsigned x0, unsigned x1) {
    const unsigned ks0 = 0u, ks1 = 42u, ks2 = 0u ^ 42u ^ 0x1BD11BDAu;
    x0 += ks0; x1 += ks1;
#define TF_R(r) { x0 += x1; x1 = __funnelshift_l(x1, x1, (r)); x1 ^= x0; }
    TF_R(13) TF_R(15) TF_R(26) TF_R(6)
    x0 += ks1; x1 += ks2 + 1u;
    TF_R(17) TF_R(29) TF_R(16) TF_R(24)
    x0 += ks2; x1 += ks0 + 2u;
    TF_R(13) TF_R(15) TF_R(26) TF_R(6)
    x0 += ks0; x1 += ks1 + 3u;
    TF_R(17) TF_R(29) TF_R(16) TF_R(24)
    x0 += ks1; x1 += ks2 + 4u;
    TF_R(13) TF_R(15) TF_R(26) TF_R(6)
    x0 += ks2; x1 += ks0 + 5u;
#undef TF_R
    return make_uint2(x0, x1);
}

__global__ void __launch_bounds__(256) k_mask() {
    unsigned p = blockIdx.x * 256u + threadIdx.x;
    uint2 o = threefry2x32_0_42(0u, p);
    unsigned bits = o.x ^ o.y;
    unsigned m = __ballot_sync(0xffffffffu, (int)bits >= 0);
    if ((threadIdx.x & 31) == 0) g_mask[p >> 5] = m;
}

// ---------------- fp32 GEMM, K=128 fixed, 128 rows x BN cols per block ----------------
template <int BN, int TN>
__device__ __forceinline__ void gemm_body(const float* __restrict__ A,
                                          const float* __restrict__ W,
                                          float* __restrict__ C) {
    __shared__ float As[16][128];
    __shared__ float Ws[16][BN];
    const int tid = threadIdx.x;
    const int tx = tid & 15;
    const int ty = tid >> 4;
    const int row0 = blockIdx.x * 128;

    float acc[8][TN];
#pragma unroll
    for (int i = 0; i < 8; i++)
#pragma unroll
        for (int j = 0; j < TN; j++) acc[i][j] = 0.f;

    const int ar = tid >> 1;
    const int ak = (tid & 1) * 8;
    const int grow = row0 + ar;
    const bool av = (grow < NN);
    const float* Arow = A + (size_t)(av ? grow : 0) * 128;

    for (int k0 = 0; k0 < 128; k0 += 16) {
        float4 a0 = make_float4(0.f, 0.f, 0.f, 0.f), a1 = a0;
        if (av) {
            a0 = *(const float4*)(Arow + k0 + ak);
            a1 = *(const float4*)(Arow + k0 + ak + 4);
        }
        As[ak + 0][ar] = a0.x; As[ak + 1][ar] = a0.y;
        As[ak + 2][ar] = a0.z; As[ak + 3][ar] = a0.w;
        As[ak + 4][ar] = a1.x; As[ak + 5][ar] = a1.y;
        As[ak + 6][ar] = a1.z; As[ak + 7][ar] = a1.w;
        constexpr int W4 = BN / 4;
#pragma unroll
        for (int it = 0; it < (16 * W4) / 256; it++) {
            int idx = tid + it * 256;
            int kk = idx / W4, c4 = idx % W4;
            *(float4*)&Ws[kk][c4 * 4] = *(const float4*)(W + (size_t)(k0 + kk) * BN + c4 * 4);
        }
        __syncthreads();
#pragma unroll
        for (int kk = 0; kk < 16; kk++) {
            float4 av0 = *(const float4*)&As[kk][ty * 8];
            float4 av1 = *(const float4*)&As[kk][ty * 8 + 4];
            float a[8] = {av0.x, av0.y, av0.z, av0.w, av1.x, av1.y, av1.z, av1.w};
            float b[TN];
#pragma unroll
            for (int j = 0; j < TN; j += 4) {
                float4 bv = *(const float4*)&Ws[kk][tx * TN + j];
                b[j] = bv.x; b[j + 1] = bv.y; b[j + 2] = bv.z; b[j + 3] = bv.w;
            }
#pragma unroll
            for (int i = 0; i < 8; i++)
#pragma unroll
                for (int j = 0; j < TN; j++) acc[i][j] = fmaf(a[i], b[j], acc[i][j]);
        }
        __syncthreads();
    }
#pragma unroll
    for (int i = 0; i < 8; i++) {
        int r = row0 + ty * 8 + i;
        if (r < NN) {
#pragma unroll
            for (int j = 0; j < TN; j += 4) {
                *(float4*)(C + (size_t)r * BN + tx * TN + j) =
                    make_float4(acc[i][j], acc[i][j + 1], acc[i][j + 2], acc[i][j + 3]);
            }
        }
    }
}

__global__ void __launch_bounds__(256) k_gemm1(const float* __restrict__ A,
                                               const float* __restrict__ W) {
    gemm_body<128, 8>(A, W, g_h1);
}
__global__ void __launch_bounds__(256) k_gemm2(const float* __restrict__ W) {
    gemm_body<64, 4>(g_agg, W, g_h2);
}

// ---------------- layer-1 aggregation: warp per node, fused epilogue ----------------
// agg[d] = relu( sum_{s in N(d)} h1[s]*dinv[s]*dinv[d] + h1[d]*dinv[d]^2 + b1 ) * mask * 2
__global__ void __launch_bounds__(256) k_agg1(const float* __restrict__ b1) {
    int d = (blockIdx.x * 256 + threadIdx.x) >> 5;
    if (d >= NN) return;
    int lane = threadIdx.x & 31;
    float dind = g_dinv[d];

    float4 h = *(const float4*)(g_h1 + (size_t)d * 128 + lane * 4);
    float s2 = dind * dind;
    float4 acc = make_float4(h.x * s2, h.y * s2, h.z * s2, h.w * s2);

    int beg = g_off[d], end = g_off[d + 1];
    for (int i = beg; i < end; i++) {
        int s = g_srcs[i];                      // broadcast within warp
        float nw = g_dinv[s] * dind;
        float4 hv = *(const float4*)(g_h1 + (size_t)s * 128 + lane * 4);
        acc.x = fmaf(hv.x, nw, acc.x);
        acc.y = fmaf(hv.y, nw, acc.y);
        acc.z = fmaf(hv.z, nw, acc.z);
        acc.w = fmaf(hv.w, nw, acc.w);
    }

    int f = lane * 4;
    float4 bv = *(const float4*)(b1 + f);
    unsigned m = g_mask[((size_t)d * 128 + f) >> 5];
    int bit = f & 31;
    acc.x = fmaxf(acc.x + bv.x, 0.f) * (((m >> (bit + 0)) & 1u) ? 2.f : 0.f);
    acc.y = fmaxf(acc.y + bv.y, 0.f) * (((m >> (bit + 1)) & 1u) ? 2.f : 0.f);
    acc.z = fmaxf(acc.z + bv.z, 0.f) * (((m >> (bit + 2)) & 1u) ? 2.f : 0.f);
    acc.w = fmaxf(acc.w + bv.w, 0.f) * (((m >> (bit + 3)) & 1u) ? 2.f : 0.f);
    *(float4*)(g_agg + (size_t)d * 128 + lane * 4) = acc;
}

// ---------------- layer-2 aggregation: half warp per node, fused epilogue ----------------
// out[d] = sum_{s} h2[s]*norm + h2[d]*dinv^2 + b2
__global__ void __launch_bounds__(256) k_agg2(const float* __restrict__ b2,
                                              float* __restrict__ out) {
    int t = blockIdx.x * 256 + threadIdx.x;
    int d = t >> 4;
    if (d >= NN) return;
    int l = t & 15;
    float dind = g_dinv[d];

    float4 h = *(const float4*)(g_h2 + (size_t)d * 64 + l * 4);
    float s2 = dind * dind;
    float4 acc = make_float4(h.x * s2, h.y * s2, h.z * s2, h.w * s2);

    int beg = g_off[d], end = g_off[d + 1];
    for (int i = beg; i < end; i++) {
        int s = g_srcs[i];
        float nw = g_dinv[s] * dind;
        float4 hv = *(const float4*)(g_h2 + (size_t)s * 64 + l * 4);
        acc.x = fmaf(hv.x, nw, acc.x);
        acc.y = fmaf(hv.y, nw, acc.y);
        acc.z = fmaf(hv.z, nw, acc.z);
        acc.w = fmaf(hv.w, nw, acc.w);
    }

    float4 bv = *(const float4*)(b2 + l * 4);
    acc.x += bv.x; acc.y += bv.y; acc.z += bv.z; acc.w += bv.w;
    *(float4*)(out + (size_t)d * 64 + l * 4) = acc;
}

// ---------------- launch ----------------
extern "C" void kernel_launch(void* const* d_in, const int* in_sizes, int n_in,
                              void* d_out, int out_size) {
    const float* x  = (const float*)d_in[0];
    const int*   ei = (const int*)d_in[1];
    const float* W1 = (const float*)d_in[2];
    const float* b1 = (const float*)d_in[3];
    const float* W2 = (const float*)d_in[4];
    const float* b2 = (const float*)d_in[5];
    const int* src = ei;
    const int* dst = ei + NE;
    float* out = (float*)d_out;

    // CSR build
    k_deg_zero<<<NBLK, 256>>>();
    k_deg_count<<<(NE + 255) / 256, 256>>>(dst);
    k_blocksum<<<NBLK, 256>>>();
    k_scan_bsum<<<1, 512>>>();
    k_nodeoff<<<NBLK, 256>>>();
    k_fill<<<(NE + 255) / 256, 256>>>(src, dst);

    // dropout mask (independent)
    k_mask<<<(NN * FH) / 256, 256>>>();

    // layer 1
    k_gemm1<<<(NN + 127) / 128, 256>>>(x, W1);
    k_agg1<<<(NN * 32 + 255) / 256, 256>>>(b1);

    // layer 2
    k_gemm2<<<(NN + 127) / 128, 256>>>(W2);
    k_agg2<<<(NN * 16 + 255) / 256, 256>>>(b2, out);
}

// round 4
// speedup vs baseline: 1.7388x; 1.0564x over previous
#include <cuda_runtime.h>
#include <cstdint>

#define NN 100000
#define NE 1600000
#define FH 128
#define FO 64
#define NMASK_WORDS 400000   // NN*FH/32
#define NBLK 391             // ceil(NN/256)

__device__ int      g_dege[NN];      // real in-degree (no self loop)
__device__ float    g_dinv[NN];
__device__ int      g_off[NN + 1];
__device__ int      g_cur[NN];
__device__ int      g_srcs[NE];
__device__ int      g_bsum[NBLK];
__device__ int      g_boff[NBLK];
__device__ float    g_h1[(size_t)NN * FH];
__device__ float    g_agg[(size_t)NN * FH];
__device__ float    g_h2[(size_t)NN * FO];   // pre-scaled by dinv[row] in GEMM2 epilogue
__device__ unsigned g_mask[NMASK_WORDS];

// ---------------- degree ----------------
__global__ void k_deg_zero() {
    int i = blockIdx.x * blockDim.x + threadIdx.x;
    if (i < NN) g_dege[i] = 0;
}
__global__ void k_deg_count(const int* __restrict__ dst) {
    int e = blockIdx.x * blockDim.x + threadIdx.x;
    if (e < NE) atomicAdd(&g_dege[dst[e]], 1);
}

// ---------------- CSR build: two-level exclusive scan ----------------
__global__ void __launch_bounds__(256) k_blocksum() {
    __shared__ int sh[8];
    int i = blockIdx.x * 256 + threadIdx.x;
    int v = (i < NN) ? g_dege[i] : 0;
#pragma unroll
    for (int o = 16; o > 0; o >>= 1) v += __shfl_down_sync(0xffffffffu, v, o);
    if ((threadIdx.x & 31) == 0) sh[threadIdx.x >> 5] = v;
    __syncthreads();
    if (threadIdx.x < 8) {
        int t = sh[threadIdx.x];
#pragma unroll
        for (int o = 4; o > 0; o >>= 1) t += __shfl_down_sync(0xffu, t, o);
        if (threadIdx.x == 0) g_bsum[blockIdx.x] = t;
    }
}

__global__ void __launch_bounds__(512) k_scan_bsum() {
    __shared__ int sh[512];
    int t = threadIdx.x;
    sh[t] = (t < NBLK) ? g_bsum[t] : 0;
    __syncthreads();
#pragma unroll
    for (int o = 1; o < 512; o <<= 1) {
        int v = (t >= o) ? sh[t - o] : 0;
        __syncthreads();
        sh[t] += v;
        __syncthreads();
    }
    if (t < NBLK) g_boff[t] = sh[t] - g_bsum[t];   // exclusive
}

__global__ void __launch_bounds__(256) k_nodeoff() {
    __shared__ int sh[256];
    int i = blockIdx.x * 256 + threadIdx.x;
    int t = threadIdx.x;
    int d = (i < NN) ? g_dege[i] : 0;
    sh[t] = d;
    __syncthreads();
#pragma unroll
    for (int o = 1; o < 256; o <<= 1) {
        int v = (t >= o) ? sh[t - o] : 0;
        __syncthreads();
        sh[t] += v;
        __syncthreads();
    }
    if (i < NN) {
        int off = g_boff[blockIdx.x] + sh[t] - d;   // exclusive
        g_off[i] = off;
        g_cur[i] = off;
        g_dinv[i] = rsqrtf((float)(d + 1));         // +1 self loop
        if (i == NN - 1) g_off[NN] = off + d;
    }
}

__global__ void k_fill(const int* __restrict__ src, const int* __restrict__ dst) {
    int e = blockIdx.x * blockDim.x + threadIdx.x;
    if (e >= NE) return;
    int slot = atomicAdd(&g_cur[dst[e]], 1);
    g_srcs[slot] = src[e];
}

// ---------------- JAX threefry2x32 dropout mask (partitionable path) ----------------
__device__ __forceinline__ uint2 threefry2x32_0_42(unsigned x0, unsigned x1) {
    const unsigned ks0 = 0u, ks1 = 42u, ks2 = 0u ^ 42u ^ 0x1BD11BDAu;
    x0 += ks0; x1 += ks1;
#define TF_R(r) { x0 += x1; x1 = __funnelshift_l(x1, x1, (r)); x1 ^= x0; }
    TF_R(13) TF_R(15) TF_R(26) TF_R(6)
    x0 += ks1; x1 += ks2 + 1u;
    TF_R(17) TF_R(29) TF_R(16) TF_R(24)
    x0 += ks2; x1 += ks0 + 2u;
    TF_R(13) TF_R(15) TF_R(26) TF_R(6)
    x0 += ks0; x1 += ks1 + 3u;
    TF_R(17) TF_R(29) TF_R(16) TF_R(24)
    x0 += ks1; x1 += ks2 + 4u;
    TF_R(13) TF_R(15) TF_R(26) TF_R(6)
    x0 += ks2; x1 += ks0 + 5u;
#undef TF_R
    return make_uint2(x0, x1);
}

__global__ void __launch_bounds__(256) k_mask() {
    unsigned p = blockIdx.x * 256u + threadIdx.x;
    uint2 o = threefry2x32_0_42(0u, p);
    unsigned bits = o.x ^ o.y;
    unsigned m = __ballot_sync(0xffffffffu, (int)bits >= 0);
    if ((threadIdx.x & 31) == 0) g_mask[p >> 5] = m;
}

// ---------------- fp32 GEMM, K=128 fixed, 128 rows x BN cols per block ----------------
// SCALE: multiply output row r by g_dinv[r] (fused norm for layer 2)
template <int BN, int TN, bool SCALE>
__device__ __forceinline__ void gemm_body(const float* __restrict__ A,
                                          const float* __restrict__ W,
                                          float* __restrict__ C) {
    __shared__ float As[16][128];
    __shared__ float Ws[16][BN];
    const int tid = threadIdx.x;
    const int tx = tid & 15;
    const int ty = tid >> 4;
    const int row0 = blockIdx.x * 128;

    float acc[8][TN];
#pragma unroll
    for (int i = 0; i < 8; i++)
#pragma unroll
        for (int j = 0; j < TN; j++) acc[i][j] = 0.f;

    const int ar = tid >> 1;
    const int ak = (tid & 1) * 8;
    const int grow = row0 + ar;
    const bool av = (grow < NN);
    const float* Arow = A + (size_t)(av ? grow : 0) * 128;

    for (int k0 = 0; k0 < 128; k0 += 16) {
        float4 a0 = make_float4(0.f, 0.f, 0.f, 0.f), a1 = a0;
        if (av) {
            a0 = *(const float4*)(Arow + k0 + ak);
            a1 = *(const float4*)(Arow + k0 + ak + 4);
        }
        As[ak + 0][ar] = a0.x; As[ak + 1][ar] = a0.y;
        As[ak + 2][ar] = a0.z; As[ak + 3][ar] = a0.w;
        As[ak + 4][ar] = a1.x; As[ak + 5][ar] = a1.y;
        As[ak + 6][ar] = a1.z; As[ak + 7][ar] = a1.w;
        constexpr int W4 = BN / 4;
#pragma unroll
        for (int it = 0; it < (16 * W4) / 256; it++) {
            int idx = tid + it * 256;
            int kk = idx / W4, c4 = idx % W4;
            *(float4*)&Ws[kk][c4 * 4] = *(const float4*)(W + (size_t)(k0 + kk) * BN + c4 * 4);
        }
        __syncthreads();
#pragma unroll
        for (int kk = 0; kk < 16; kk++) {
            float4 av0 = *(const float4*)&As[kk][ty * 8];
            float4 av1 = *(const float4*)&As[kk][ty * 8 + 4];
            float a[8] = {av0.x, av0.y, av0.z, av0.w, av1.x, av1.y, av1.z, av1.w};
            float b[TN];
#pragma unroll
            for (int j = 0; j < TN; j += 4) {
                float4 bv = *(const float4*)&Ws[kk][tx * TN + j];
                b[j] = bv.x; b[j + 1] = bv.y; b[j + 2] = bv.z; b[j + 3] = bv.w;
            }
#pragma unroll
            for (int i = 0; i < 8; i++)
#pragma unroll
                for (int j = 0; j < TN; j++) acc[i][j] = fmaf(a[i], b[j], acc[i][j]);
        }
        __syncthreads();
    }
#pragma unroll
    for (int i = 0; i < 8; i++) {
        int r = row0 + ty * 8 + i;
        if (r < NN) {
            float sc = SCALE ? __ldg(g_dinv + r) : 1.f;
#pragma unroll
            for (int j = 0; j < TN; j += 4) {
                *(float4*)(C + (size_t)r * BN + tx * TN + j) =
                    make_float4(acc[i][j] * sc, acc[i][j + 1] * sc,
                                acc[i][j + 2] * sc, acc[i][j + 3] * sc);
            }
        }
    }
}

__global__ void __launch_bounds__(256) k_gemm1(const float* __restrict__ A,
                                               const float* __restrict__ W) {
    gemm_body<128, 8, false>(A, W, g_h1);
}
__global__ void __launch_bounds__(256) k_gemm2(const float* __restrict__ W) {
    gemm_body<64, 4, true>(g_agg, W, g_h2);
}

// ---------------- layer-1 aggregation: warp per node, fused epilogue, unroll-4 ----------------
// agg[d] = relu( (sum_s h1[s]*dinv[s])*dinv[d] + h1[d]*dinv[d]^2 + b1 ) * mask * 2
__global__ void __launch_bounds__(256) k_agg1(const float* __restrict__ b1) {
    int d = (blockIdx.x * 256 + threadIdx.x) >> 5;
    if (d >= NN) return;
    int lane = threadIdx.x & 31;
    float dind = __ldg(g_dinv + d);

    const float4* hbase = (const float4*)g_h1;
    float4 h = __ldg(hbase + (size_t)d * 32 + lane);

    float4 ae = make_float4(0.f, 0.f, 0.f, 0.f);   // sum of h1[s]*dinv[s]
    int beg = __ldg(g_off + d), end = __ldg(g_off + d + 1);
    int i = beg;
    for (; i + 4 <= end; i += 4) {
        int s0 = __ldg(g_srcs + i + 0);
        int s1 = __ldg(g_srcs + i + 1);
        int s2 = __ldg(g_srcs + i + 2);
        int s3 = __ldg(g_srcs + i + 3);
        float n0 = __ldg(g_dinv + s0), n1 = __ldg(g_dinv + s1);
        float n2 = __ldg(g_dinv + s2), n3 = __ldg(g_dinv + s3);
        float4 v0 = __ldg(hbase + (size_t)s0 * 32 + lane);
        float4 v1 = __ldg(hbase + (size_t)s1 * 32 + lane);
        float4 v2 = __ldg(hbase + (size_t)s2 * 32 + lane);
        float4 v3 = __ldg(hbase + (size_t)s3 * 32 + lane);
        ae.x = fmaf(v0.x, n0, ae.x); ae.y = fmaf(v0.y, n0, ae.y);
        ae.z = fmaf(v0.z, n0, ae.z); ae.w = fmaf(v0.w, n0, ae.w);
        ae.x = fmaf(v1.x, n1, ae.x); ae.y = fmaf(v1.y, n1, ae.y);
        ae.z = fmaf(v1.z, n1, ae.z); ae.w = fmaf(v1.w, n1, ae.w);
        ae.x = fmaf(v2.x, n2, ae.x); ae.y = fmaf(v2.y, n2, ae.y);
        ae.z = fmaf(v2.z, n2, ae.z); ae.w = fmaf(v2.w, n2, ae.w);
        ae.x = fmaf(v3.x, n3, ae.x); ae.y = fmaf(v3.y, n3, ae.y);
        ae.z = fmaf(v3.z, n3, ae.z); ae.w = fmaf(v3.w, n3, ae.w);
    }
    for (; i < end; i++) {
        int s = __ldg(g_srcs + i);
        float n = __ldg(g_dinv + s);
        float4 v = __ldg(hbase + (size_t)s * 32 + lane);
        ae.x = fmaf(v.x, n, ae.x); ae.y = fmaf(v.y, n, ae.y);
        ae.z = fmaf(v.z, n, ae.z); ae.w = fmaf(v.w, n, ae.w);
    }

    float s2 = dind * dind;
    float4 acc;
    acc.x = fmaf(ae.x, dind, h.x * s2);
    acc.y = fmaf(ae.y, dind, h.y * s2);
    acc.z = fmaf(ae.z, dind, h.z * s2);
    acc.w = fmaf(ae.w, dind, h.w * s2);

    int f = lane * 4;
    float4 bv = __ldg((const float4*)(b1 + f));
    unsigned m = g_mask[((size_t)d * 128 + f) >> 5];
    int bit = f & 31;
    acc.x = fmaxf(acc.x + bv.x, 0.f) * (((m >> (bit + 0)) & 1u) ? 2.f : 0.f);
    acc.y = fmaxf(acc.y + bv.y, 0.f) * (((m >> (bit + 1)) & 1u) ? 2.f : 0.f);
    acc.z = fmaxf(acc.z + bv.z, 0.f) * (((m >> (bit + 2)) & 1u) ? 2.f : 0.f);
    acc.w = fmaxf(acc.w + bv.w, 0.f) * (((m >> (bit + 3)) & 1u) ? 2.f : 0.f);
    *(float4*)(g_agg + (size_t)d * 128 + lane * 4) = acc;
}

// ---------------- layer-2 aggregation: half warp per node, h2 pre-scaled by dinv ----------------
// out[d] = (sum_s h2s[s] + h2s[d]) * dinv[d] + b2
__global__ void __launch_bounds__(256) k_agg2(const float* __restrict__ b2,
                                              float* __restrict__ out) {
    int t = blockIdx.x * 256 + threadIdx.x;
    int d = t >> 4;
    if (d >= NN) return;
    int l = t & 15;
    float dind = __ldg(g_dinv + d);

    const float4* hbase = (const float4*)g_h2;
    float4 acc = __ldg(hbase + (size_t)d * 16 + l);   // self term (pre-scaled)

    int beg = __ldg(g_off + d), end = __ldg(g_off + d + 1);
    int i = beg;
    for (; i + 4 <= end; i += 4) {
        int s0 = __ldg(g_srcs + i + 0);
        int s1 = __ldg(g_srcs + i + 1);
        int s2 = __ldg(g_srcs + i + 2);
        int s3 = __ldg(g_srcs + i + 3);
        float4 v0 = __ldg(hbase + (size_t)s0 * 16 + l);
        float4 v1 = __ldg(hbase + (size_t)s1 * 16 + l);
        float4 v2 = __ldg(hbase + (size_t)s2 * 16 + l);
        float4 v3 = __ldg(hbase + (size_t)s3 * 16 + l);
        acc.x += v0.x + v1.x + v2.x + v3.x;
        acc.y += v0.y + v1.y + v2.y + v3.y;
        acc.z += v0.z + v1.z + v2.z + v3.z;
        acc.w += v0.w + v1.w + v2.w + v3.w;
    }
    for (; i < end; i++) {
        int s = __ldg(g_srcs + i);
        float4 v = __ldg(hbase + (size_t)s * 16 + l);
        acc.x += v.x; acc.y += v.y; acc.z += v.z; acc.w += v.w;
    }

    float4 bv = __ldg((const float4*)(b2 + l * 4));
    acc.x = fmaf(acc.x, dind, bv.x);
    acc.y = fmaf(acc.y, dind, bv.y);
    acc.z = fmaf(acc.z, dind, bv.z);
    acc.w = fmaf(acc.w, dind, bv.w);
    *(float4*)(out + (size_t)d * 64 + l * 4) = acc;
}

// ---------------- launch: fork mask & GEMM1 onto side streams, join before agg1 ----------------
extern "C" void kernel_launch(void* const* d_in, const int* in_sizes, int n_in,
                              void* d_out, int out_size) {
    const float* x  = (const float*)d_in[0];
    const int*   ei = (const int*)d_in[1];
    const float* W1 = (const float*)d_in[2];
    const float* b1 = (const float*)d_in[3];
    const float* W2 = (const float*)d_in[4];
    const float* b2 = (const float*)d_in[5];
    const int* src = ei;
    const int* dst = ei + NE;
    float* out = (float*)d_out;

    static cudaStream_t sA = nullptr, sB = nullptr;
    static cudaEvent_t evRoot = nullptr, evA = nullptr, evB = nullptr;
    if (sA == nullptr) {
        cudaStreamCreateWithFlags(&sA, cudaStreamNonBlocking);
        cudaStreamCreateWithFlags(&sB, cudaStreamNonBlocking);
        cudaEventCreateWithFlags(&evRoot, cudaEventDisableTiming);
        cudaEventCreateWithFlags(&evA, cudaEventDisableTiming);
        cudaEventCreateWithFlags(&evB, cudaEventDisableTiming);
    }

    // fork point on the (captured) default stream
    cudaEventRecord(evRoot, 0);
    cudaStreamWaitEvent(sA, evRoot, 0);
    cudaStreamWaitEvent(sB, evRoot, 0);

    // stream A: dropout mask
    k_mask<<<(NN * FH) / 256, 256, 0, sA>>>();
    cudaEventRecord(evA, sA);

    // stream B: GEMM1 (largest independent chunk)
    k_gemm1<<<(NN + 127) / 128, 256, 0, sB>>>(x, W1);
    cudaEventRecord(evB, sB);

    // default stream: CSR build
    k_deg_zero<<<NBLK, 256>>>();
    k_deg_count<<<(NE + 255) / 256, 256>>>(dst);
    k_blocksum<<<NBLK, 256>>>();
    k_scan_bsum<<<1, 512>>>();
    k_nodeoff<<<NBLK, 256>>>();
    k_fill<<<(NE + 255) / 256, 256>>>(src, dst);

    // join
    cudaStreamWaitEvent(0, evA, 0);
    cudaStreamWaitEvent(0, evB, 0);

    // layer 1 aggregation (+relu+dropout), layer 2
    k_agg1<<<(NN * 32 + 255) / 256, 256>>>(b1);
    k_gemm2<<<(NN + 127) / 128, 256>>>(W2);
    k_agg2<<<(NN * 16 + 255) / 256, 256>>>(b2, out);
}

// round 5
// speedup vs baseline: 2.3131x; 1.3303x over previous
#include <cuda_runtime.h>
#include <cstdint>

#define NN 100000
#define NE 1600000
#define FH 128
#define FO 64
#define NMASK_WORDS 400000   // NN*FH/32
#define NBLK 391             // ceil(NN/256)

__device__ int      g_dege[NN];      // real in-degree (no self loop)
__device__ float    g_dinv[NN];
__device__ int      g_off[NN + 1];
__device__ int      g_cur[NN];
__device__ int      g_srcs[NE];
__device__ int      g_bsum[NBLK];
__device__ int      g_boff[NBLK];
__device__ float    g_h1[(size_t)NN * FH];
__device__ float    g_agg[(size_t)NN * FH];
__device__ float    g_h2[(size_t)NN * FO];   // pre-scaled by dinv[row] in GEMM2 epilogue
__device__ unsigned g_mask[NMASK_WORDS];

// ---------------- degree ----------------
__global__ void k_deg_zero() {
    int i = blockIdx.x * blockDim.x + threadIdx.x;
    if (i < NN) g_dege[i] = 0;
}
__global__ void k_deg_count(const int* __restrict__ dst) {
    int e = blockIdx.x * blockDim.x + threadIdx.x;
    if (e < NE) atomicAdd(&g_dege[dst[e]], 1);
}

// ---------------- CSR build: two-level exclusive scan ----------------
__global__ void __launch_bounds__(256) k_blocksum() {
    __shared__ int sh[8];
    int i = blockIdx.x * 256 + threadIdx.x;
    int v = (i < NN) ? g_dege[i] : 0;
#pragma unroll
    for (int o = 16; o > 0; o >>= 1) v += __shfl_down_sync(0xffffffffu, v, o);
    if ((threadIdx.x & 31) == 0) sh[threadIdx.x >> 5] = v;
    __syncthreads();
    if (threadIdx.x < 8) {
        int t = sh[threadIdx.x];
#pragma unroll
        for (int o = 4; o > 0; o >>= 1) t += __shfl_down_sync(0xffu, t, o);
        if (threadIdx.x == 0) g_bsum[blockIdx.x] = t;
    }
}

__global__ void __launch_bounds__(512) k_scan_bsum() {
    __shared__ int sh[512];
    int t = threadIdx.x;
    sh[t] = (t < NBLK) ? g_bsum[t] : 0;
    __syncthreads();
#pragma unroll
    for (int o = 1; o < 512; o <<= 1) {
        int v = (t >= o) ? sh[t - o] : 0;
        __syncthreads();
        sh[t] += v;
        __syncthreads();
    }
    if (t < NBLK) g_boff[t] = sh[t] - g_bsum[t];   // exclusive
}

__global__ void __launch_bounds__(256) k_nodeoff() {
    __shared__ int sh[256];
    int i = blockIdx.x * 256 + threadIdx.x;
    int t = threadIdx.x;
    int d = (i < NN) ? g_dege[i] : 0;
    sh[t] = d;
    __syncthreads();
#pragma unroll
    for (int o = 1; o < 256; o <<= 1) {
        int v = (t >= o) ? sh[t - o] : 0;
        __syncthreads();
        sh[t] += v;
        __syncthreads();
    }
    if (i < NN) {
        int off = g_boff[blockIdx.x] + sh[t] - d;   // exclusive
        g_off[i] = off;
        g_cur[i] = off;
        g_dinv[i] = rsqrtf((float)(d + 1));         // +1 self loop
        if (i == NN - 1) g_off[NN] = off + d;
    }
}

__global__ void k_fill(const int* __restrict__ src, const int* __restrict__ dst) {
    int e = blockIdx.x * blockDim.x + threadIdx.x;
    if (e >= NE) return;
    int slot = atomicAdd(&g_cur[dst[e]], 1);
    g_srcs[slot] = src[e];
}

// ---------------- JAX threefry2x32 dropout mask (partitionable path) ----------------
__device__ __forceinline__ uint2 threefry2x32_0_42(unsigned x0, unsigned x1) {
    const unsigned ks0 = 0u, ks1 = 42u, ks2 = 0u ^ 42u ^ 0x1BD11BDAu;
    x0 += ks0; x1 += ks1;
#define TF_R(r) { x0 += x1; x1 = __funnelshift_l(x1, x1, (r)); x1 ^= x0; }
    TF_R(13) TF_R(15) TF_R(26) TF_R(6)
    x0 += ks1; x1 += ks2 + 1u;
    TF_R(17) TF_R(29) TF_R(16) TF_R(24)
    x0 += ks2; x1 += ks0 + 2u;
    TF_R(13) TF_R(15) TF_R(26) TF_R(6)
    x0 += ks0; x1 += ks1 + 3u;
    TF_R(17) TF_R(29) TF_R(16) TF_R(24)
    x0 += ks1; x1 += ks2 + 4u;
    TF_R(13) TF_R(15) TF_R(26) TF_R(6)
    x0 += ks2; x1 += ks0 + 5u;
#undef TF_R
    return make_uint2(x0, x1);
}

__global__ void __launch_bounds__(256) k_mask() {
    unsigned p = blockIdx.x * 256u + threadIdx.x;
    uint2 o = threefry2x32_0_42(0u, p);
    unsigned bits = o.x ^ o.y;
    unsigned m = __ballot_sync(0xffffffffu, (int)bits >= 0);
    if ((threadIdx.x & 31) == 0) g_mask[p >> 5] = m;
}

// ---------------- tf32 tensor-core GEMM: C[NN x BN] = A[NN x 128] * W[128 x BN] ----------------
__device__ __forceinline__ uint32_t f2tf(float f) {
    uint32_t u; asm("cvt.rna.tf32.f32 %0, %1;" : "=r"(u) : "f"(f)); return u;
}

__device__ __forceinline__ void mma_tf32(float* c, const uint32_t* a, const uint32_t* b) {
    asm volatile(
        "mma.sync.aligned.m16n8k8.row.col.f32.tf32.tf32.f32 "
        "{%0,%1,%2,%3}, {%4,%5,%6,%7}, {%8,%9}, {%0,%1,%2,%3};\n"
        : "+f"(c[0]), "+f"(c[1]), "+f"(c[2]), "+f"(c[3])
        : "r"(a[0]), "r"(a[1]), "r"(a[2]), "r"(a[3]), "r"(b[0]), "r"(b[1]));
}

// 128 rows x BN cols per block, 8 warps: warp_m = wid&3 (32 rows), warp_n = wid>>2 (BN/2 cols)
template <int BN, bool SCALE>
__device__ __forceinline__ void gemm_tf32_body(const float* __restrict__ A,
                                               const float* __restrict__ W,
                                               float* __restrict__ C) {
    __shared__ uint32_t As[128][36];   // [row][k]  bank = (4r+k)%32 = lane -> conflict free
    __shared__ uint32_t Wt[BN][36];    // [n][k]    bank = (4n+k)%32 = lane -> conflict free
    const int tid = threadIdx.x;
    const int lane = tid & 31, wid = tid >> 5;
    const int warp_m = wid & 3, warp_n = wid >> 2;
    const int row0 = blockIdx.x * 128;
    constexpr int WN = BN / 2;     // warp n-extent
    constexpr int TN = WN / 8;     // n-tiles per warp

    float c[2][TN][4];
#pragma unroll
    for (int i = 0; i < 2; i++)
#pragma unroll
        for (int j = 0; j < TN; j++)
#pragma unroll
            for (int q = 0; q < 4; q++) c[i][j][q] = 0.f;

    for (int k0 = 0; k0 < 128; k0 += 32) {
        // stage A chunk: 128x32, cvt to tf32
#pragma unroll
        for (int it = 0; it < 4; it++) {
            int idx = tid + it * 256;
            int r = idx >> 3, cg = (idx & 7) * 4;
            int gr = row0 + r; if (gr >= NN) gr = 0;
            float4 v = __ldg((const float4*)(A + (size_t)gr * 128 + k0 + cg));
            *(uint4*)&As[r][cg] = make_uint4(f2tf(v.x), f2tf(v.y), f2tf(v.z), f2tf(v.w));
        }
        // stage W chunk transposed: Wt[n][k], 4 k's per thread (coalesced over n)
        constexpr int WIT = (32 * BN) / (256 * 4);
#pragma unroll
        for (int it = 0; it < WIT; it++) {
            int idx = tid + it * 256;
            int n = idx % BN, g = idx / BN;      // g in 0..7
            uint32_t w0 = f2tf(__ldg(W + (size_t)(k0 + 4 * g + 0) * BN + n));
            uint32_t w1 = f2tf(__ldg(W + (size_t)(k0 + 4 * g + 1) * BN + n));
            uint32_t w2 = f2tf(__ldg(W + (size_t)(k0 + 4 * g + 2) * BN + n));
            uint32_t w3 = f2tf(__ldg(W + (size_t)(k0 + 4 * g + 3) * BN + n));
            *(uint4*)&Wt[n][4 * g] = make_uint4(w0, w1, w2, w3);
        }
        __syncthreads();

#pragma unroll
        for (int kk = 0; kk < 4; kk++) {
            const int ac = kk * 8 + (lane & 3);
            uint32_t a[2][4];
            const int ar = warp_m * 32 + (lane >> 2);
#pragma unroll
            for (int tm = 0; tm < 2; tm++) {
                a[tm][0] = As[ar + tm * 16][ac];
                a[tm][1] = As[ar + tm * 16 + 8][ac];
                a[tm][2] = As[ar + tm * 16][ac + 4];
                a[tm][3] = As[ar + tm * 16 + 8][ac + 4];
            }
#pragma unroll
            for (int tn = 0; tn < TN; tn++) {
                uint32_t b[2];
                int bn = warp_n * WN + tn * 8 + (lane >> 2);
                b[0] = Wt[bn][ac];
                b[1] = Wt[bn][ac + 4];
                mma_tf32(c[0][tn], a[0], b);
                mma_tf32(c[1][tn], a[1], b);
            }
        }
        __syncthreads();
    }

    // epilogue: c0,c1 -> (row, 2q..2q+1), c2,c3 -> (row+8, ...)
#pragma unroll
    for (int tm = 0; tm < 2; tm++) {
        int rbase = row0 + warp_m * 32 + tm * 16 + (lane >> 2);
#pragma unroll
        for (int half = 0; half < 2; half++) {
            int rr = rbase + half * 8;
            if (rr < NN) {
                float sc = SCALE ? __ldg(g_dinv + rr) : 1.f;
#pragma unroll
                for (int tn = 0; tn < TN; tn++) {
                    int n = warp_n * WN + tn * 8 + 2 * (lane & 3);
                    *(float2*)(C + (size_t)rr * BN + n) =
                        make_float2(c[tm][tn][2 * half] * sc, c[tm][tn][2 * half + 1] * sc);
                }
            }
        }
    }
}

__global__ void __launch_bounds__(256) k_gemm1(const float* __restrict__ A,
                                               const float* __restrict__ W) {
    gemm_tf32_body<128, false>(A, W, g_h1);
}
__global__ void __launch_bounds__(256) k_gemm2(const float* __restrict__ W) {
    gemm_tf32_body<64, true>(g_agg, W, g_h2);
}

// ---------------- layer-1 aggregation: warp per node, fused epilogue, unroll-4 ----------------
__global__ void __launch_bounds__(256) k_agg1(const float* __restrict__ b1) {
    int d = (blockIdx.x * 256 + threadIdx.x) >> 5;
    if (d >= NN) return;
    int lane = threadIdx.x & 31;
    float dind = __ldg(g_dinv + d);

    const float4* hbase = (const float4*)g_h1;
    float4 h = __ldg(hbase + (size_t)d * 32 + lane);

    float4 ae = make_float4(0.f, 0.f, 0.f, 0.f);
    int beg = __ldg(g_off + d), end = __ldg(g_off + d + 1);
    int i = beg;
    for (; i + 4 <= end; i += 4) {
        int s0 = __ldg(g_srcs + i + 0);
        int s1 = __ldg(g_srcs + i + 1);
        int s2 = __ldg(g_srcs + i + 2);
        int s3 = __ldg(g_srcs + i + 3);
        float n0 = __ldg(g_dinv + s0), n1 = __ldg(g_dinv + s1);
        float n2 = __ldg(g_dinv + s2), n3 = __ldg(g_dinv + s3);
        float4 v0 = __ldg(hbase + (size_t)s0 * 32 + lane);
        float4 v1 = __ldg(hbase + (size_t)s1 * 32 + lane);
        float4 v2 = __ldg(hbase + (size_t)s2 * 32 + lane);
        float4 v3 = __ldg(hbase + (size_t)s3 * 32 + lane);
        ae.x = fmaf(v0.x, n0, ae.x); ae.y = fmaf(v0.y, n0, ae.y);
        ae.z = fmaf(v0.z, n0, ae.z); ae.w = fmaf(v0.w, n0, ae.w);
        ae.x = fmaf(v1.x, n1, ae.x); ae.y = fmaf(v1.y, n1, ae.y);
        ae.z = fmaf(v1.z, n1, ae.z); ae.w = fmaf(v1.w, n1, ae.w);
        ae.x = fmaf(v2.x, n2, ae.x); ae.y = fmaf(v2.y, n2, ae.y);
        ae.z = fmaf(v2.z, n2, ae.z); ae.w = fmaf(v2.w, n2, ae.w);
        ae.x = fmaf(v3.x, n3, ae.x); ae.y = fmaf(v3.y, n3, ae.y);
        ae.z = fmaf(v3.z, n3, ae.z); ae.w = fmaf(v3.w, n3, ae.w);
    }
    for (; i < end; i++) {
        int s = __ldg(g_srcs + i);
        float n = __ldg(g_dinv + s);
        float4 v = __ldg(hbase + (size_t)s * 32 + lane);
        ae.x = fmaf(v.x, n, ae.x); ae.y = fmaf(v.y, n, ae.y);
        ae.z = fmaf(v.z, n, ae.z); ae.w = fmaf(v.w, n, ae.w);
    }

    float s2 = dind * dind;
    float4 acc;
    acc.x = fmaf(ae.x, dind, h.x * s2);
    acc.y = fmaf(ae.y, dind, h.y * s2);
    acc.z = fmaf(ae.z, dind, h.z * s2);
    acc.w = fmaf(ae.w, dind, h.w * s2);

    int f = lane * 4;
    float4 bv = __ldg((const float4*)(b1 + f));
    unsigned m = g_mask[((size_t)d * 128 + f) >> 5];
    int bit = f & 31;
    acc.x = fmaxf(acc.x + bv.x, 0.f) * (((m >> (bit + 0)) & 1u) ? 2.f : 0.f);
    acc.y = fmaxf(acc.y + bv.y, 0.f) * (((m >> (bit + 1)) & 1u) ? 2.f : 0.f);
    acc.z = fmaxf(acc.z + bv.z, 0.f) * (((m >> (bit + 2)) & 1u) ? 2.f : 0.f);
    acc.w = fmaxf(acc.w + bv.w, 0.f) * (((m >> (bit + 3)) & 1u) ? 2.f : 0.f);
    *(float4*)(g_agg + (size_t)d * 128 + lane * 4) = acc;
}

// ---------------- layer-2 aggregation: half warp per node, h2 pre-scaled by dinv ----------------
__global__ void __launch_bounds__(256) k_agg2(const float* __restrict__ b2,
                                              float* __restrict__ out) {
    int t = blockIdx.x * 256 + threadIdx.x;
    int d = t >> 4;
    if (d >= NN) return;
    int l = t & 15;
    float dind = __ldg(g_dinv + d);

    const float4* hbase = (const float4*)g_h2;
    float4 acc = __ldg(hbase + (size_t)d * 16 + l);

    int beg = __ldg(g_off + d), end = __ldg(g_off + d + 1);
    int i = beg;
    for (; i + 4 <= end; i += 4) {
        int s0 = __ldg(g_srcs + i + 0);
        int s1 = __ldg(g_srcs + i + 1);
        int s2 = __ldg(g_srcs + i + 2);
        int s3 = __ldg(g_srcs + i + 3);
        float4 v0 = __ldg(hbase + (size_t)s0 * 16 + l);
        float4 v1 = __ldg(hbase + (size_t)s1 * 16 + l);
        float4 v2 = __ldg(hbase + (size_t)s2 * 16 + l);
        float4 v3 = __ldg(hbase + (size_t)s3 * 16 + l);
        acc.x += v0.x + v1.x + v2.x + v3.x;
        acc.y += v0.y + v1.y + v2.y + v3.y;
        acc.z += v0.z + v1.z + v2.z + v3.z;
        acc.w += v0.w + v1.w + v2.w + v3.w;
    }
    for (; i < end; i++) {
        int s = __ldg(g_srcs + i);
        float4 v = __ldg(hbase + (size_t)s * 16 + l);
        acc.x += v.x; acc.y += v.y; acc.z += v.z; acc.w += v.w;
    }

    float4 bv = __ldg((const float4*)(b2 + l * 4));
    acc.x = fmaf(acc.x, dind, bv.x);
    acc.y = fmaf(acc.y, dind, bv.y);
    acc.z = fmaf(acc.z, dind, bv.z);
    acc.w = fmaf(acc.w, dind, bv.w);
    *(float4*)(out + (size_t)d * 64 + l * 4) = acc;
}

// ---------------- launch: fork mask & GEMM1 onto side streams, join before agg1 ----------------
extern "C" void kernel_launch(void* const* d_in, const int* in_sizes, int n_in,
                              void* d_out, int out_size) {
    const float* x  = (const float*)d_in[0];
    const int*   ei = (const int*)d_in[1];
    const float* W1 = (const float*)d_in[2];
    const float* b1 = (const float*)d_in[3];
    const float* W2 = (const float*)d_in[4];
    const float* b2 = (const float*)d_in[5];
    const int* src = ei;
    const int* dst = ei + NE;
    float* out = (float*)d_out;

    static cudaStream_t sA = nullptr, sB = nullptr;
    static cudaEvent_t evRoot = nullptr, evA = nullptr, evB = nullptr;
    if (sA == nullptr) {
        cudaStreamCreateWithFlags(&sA, cudaStreamNonBlocking);
        cudaStreamCreateWithFlags(&sB, cudaStreamNonBlocking);
        cudaEventCreateWithFlags(&evRoot, cudaEventDisableTiming);
        cudaEventCreateWithFlags(&evA, cudaEventDisableTiming);
        cudaEventCreateWithFlags(&evB, cudaEventDisableTiming);
    }

    cudaEventRecord(evRoot, 0);
    cudaStreamWaitEvent(sA, evRoot, 0);
    cudaStreamWaitEvent(sB, evRoot, 0);

    // stream A: dropout mask
    k_mask<<<(NN * FH) / 256, 256, 0, sA>>>();
    cudaEventRecord(evA, sA);

    // stream B: GEMM1 (tensor cores)
    k_gemm1<<<(NN + 127) / 128, 256, 0, sB>>>(x, W1);
    cudaEventRecord(evB, sB);

    // default stream: CSR build
    k_deg_zero<<<NBLK, 256>>>();
    k_deg_count<<<(NE + 255) / 256, 256>>>(dst);
    k_blocksum<<<NBLK, 256>>>();
    k_scan_bsum<<<1, 512>>>();
    k_nodeoff<<<NBLK, 256>>>();
    k_fill<<<(NE + 255) / 256, 256>>>(src, dst);

    cudaStreamWaitEvent(0, evA, 0);
    cudaStreamWaitEvent(0, evB, 0);

    k_agg1<<<(NN * 32 + 255) / 256, 256>>>(b1);
    k_gemm2<<<(NN + 127) / 128, 256>>>(W2);
    k_agg2<<<(NN * 16 + 255) / 256, 256>>>(b2, out);
}

// round 6
// speedup vs baseline: 2.4920x; 1.0774x over previous
#include <cuda_runtime.h>
#include <cuda_fp16.h>
#include <cstdint>

#define NN 100000
#define NE 1600000
#define FH 128
#define FO 64
#define NMASK_WORDS 400000   // NN*FH/32
#define NBLK 391             // ceil(NN/256)

__device__ int      g_dege[NN];      // real in-degree (no self loop)
__device__ float    g_dinv[NN];
__device__ int      g_off[NN + 1];
__device__ int      g_cur[NN];
__device__ int      g_srcs[NE];
__device__ float    g_sw[NE];        // dinv[src] per CSR slot (sequential read in agg1)
__device__ int      g_bsum[NBLK];
__device__ int      g_boff[NBLK];
__device__ __half   g_h1[(size_t)NN * FH];   // fp16, unscaled
__device__ float    g_agg[(size_t)NN * FH];  // fp32 (GEMM2 input)
__device__ __half   g_h2[(size_t)NN * FO];   // fp16, pre-scaled by dinv[row]
__device__ unsigned g_mask[NMASK_WORDS];

// ---------------- degree ----------------
__global__ void k_deg_zero() {
    int i = blockIdx.x * blockDim.x + threadIdx.x;
    if (i < NN) g_dege[i] = 0;
}
__global__ void k_deg_count(const int* __restrict__ dst) {
    int e = blockIdx.x * blockDim.x + threadIdx.x;
    if (e < NE) atomicAdd(&g_dege[dst[e]], 1);
}

// ---------------- CSR build: two-level exclusive scan ----------------
__global__ void __launch_bounds__(256) k_blocksum() {
    __shared__ int sh[8];
    int i = blockIdx.x * 256 + threadIdx.x;
    int v = (i < NN) ? g_dege[i] : 0;
#pragma unroll
    for (int o = 16; o > 0; o >>= 1) v += __shfl_down_sync(0xffffffffu, v, o);
    if ((threadIdx.x & 31) == 0) sh[threadIdx.x >> 5] = v;
    __syncthreads();
    if (threadIdx.x < 8) {
        int t = sh[threadIdx.x];
#pragma unroll
        for (int o = 4; o > 0; o >>= 1) t += __shfl_down_sync(0xffu, t, o);
        if (threadIdx.x == 0) g_bsum[blockIdx.x] = t;
    }
}

__global__ void __launch_bounds__(512) k_scan_bsum() {
    __shared__ int sh[512];
    int t = threadIdx.x;
    sh[t] = (t < NBLK) ? g_bsum[t] : 0;
    __syncthreads();
#pragma unroll
    for (int o = 1; o < 512; o <<= 1) {
        int v = (t >= o) ? sh[t - o] : 0;
        __syncthreads();
        sh[t] += v;
        __syncthreads();
    }
    if (t < NBLK) g_boff[t] = sh[t] - g_bsum[t];   // exclusive
}

__global__ void __launch_bounds__(256) k_nodeoff() {
    __shared__ int sh[256];
    int i = blockIdx.x * 256 + threadIdx.x;
    int t = threadIdx.x;
    int d = (i < NN) ? g_dege[i] : 0;
    sh[t] = d;
    __syncthreads();
#pragma unroll
    for (int o = 1; o < 256; o <<= 1) {
        int v = (t >= o) ? sh[t - o] : 0;
        __syncthreads();
        sh[t] += v;
        __syncthreads();
    }
    if (i < NN) {
        int off = g_boff[blockIdx.x] + sh[t] - d;   // exclusive
        g_off[i] = off;
        g_cur[i] = off;
        g_dinv[i] = rsqrtf((float)(d + 1));         // +1 self loop
        if (i == NN - 1) g_off[NN] = off + d;
    }
}

__global__ void k_fill(const int* __restrict__ src, const int* __restrict__ dst) {
    int e = blockIdx.x * blockDim.x + threadIdx.x;
    if (e >= NE) return;
    int s = src[e];
    int slot = atomicAdd(&g_cur[dst[e]], 1);
    g_srcs[slot] = s;
    g_sw[slot] = __ldg(g_dinv + s);
}

// ---------------- JAX threefry2x32 dropout mask (partitionable path) ----------------
__device__ __forceinline__ uint2 threefry2x32_0_42(unsigned x0, unsigned x1) {
    const unsigned ks0 = 0u, ks1 = 42u, ks2 = 0u ^ 42u ^ 0x1BD11BDAu;
    x0 += ks0; x1 += ks1;
#define TF_R(r) { x0 += x1; x1 = __funnelshift_l(x1, x1, (r)); x1 ^= x0; }
    TF_R(13) TF_R(15) TF_R(26) TF_R(6)
    x0 += ks1; x1 += ks2 + 1u;
    TF_R(17) TF_R(29) TF_R(16) TF_R(24)
    x0 += ks2; x1 += ks0 + 2u;
    TF_R(13) TF_R(15) TF_R(26) TF_R(6)
    x0 += ks0; x1 += ks1 + 3u;
    TF_R(17) TF_R(29) TF_R(16) TF_R(24)
    x0 += ks1; x1 += ks2 + 4u;
    TF_R(13) TF_R(15) TF_R(26) TF_R(6)
    x0 += ks2; x1 += ks0 + 5u;
#undef TF_R
    return make_uint2(x0, x1);
}

__global__ void __launch_bounds__(256) k_mask() {
    unsigned p = blockIdx.x * 256u + threadIdx.x;
    uint2 o = threefry2x32_0_42(0u, p);
    unsigned bits = o.x ^ o.y;
    unsigned m = __ballot_sync(0xffffffffu, (int)bits >= 0);
    if ((threadIdx.x & 31) == 0) g_mask[p >> 5] = m;
}

// ---------------- tf32 tensor-core GEMM -> fp16 output ----------------
__device__ __forceinline__ uint32_t f2tf(float f) {
    uint32_t u; asm("cvt.rna.tf32.f32 %0, %1;" : "=r"(u) : "f"(f)); return u;
}

__device__ __forceinline__ void mma_tf32(float* c, const uint32_t* a, const uint32_t* b) {
    asm volatile(
        "mma.sync.aligned.m16n8k8.row.col.f32.tf32.tf32.f32 "
        "{%0,%1,%2,%3}, {%4,%5,%6,%7}, {%8,%9}, {%0,%1,%2,%3};\n"
        : "+f"(c[0]), "+f"(c[1]), "+f"(c[2]), "+f"(c[3])
        : "r"(a[0]), "r"(a[1]), "r"(a[2]), "r"(a[3]), "r"(b[0]), "r"(b[1]));
}

// 128 rows x BN cols per block, 8 warps: warp_m = wid&3 (32 rows), warp_n = wid>>2 (BN/2 cols)
template <int BN, bool SCALE>
__device__ __forceinline__ void gemm_tf32_body(const float* __restrict__ A,
                                               const float* __restrict__ W,
                                               __half* __restrict__ C) {
    __shared__ uint32_t As[128][36];   // [row][k]
    __shared__ uint32_t Wt[BN][36];    // [n][k]
    const int tid = threadIdx.x;
    const int lane = tid & 31, wid = tid >> 5;
    const int warp_m = wid & 3, warp_n = wid >> 2;
    const int row0 = blockIdx.x * 128;
    constexpr int WN = BN / 2;
    constexpr int TN = WN / 8;

    float c[2][TN][4];
#pragma unroll
    for (int i = 0; i < 2; i++)
#pragma unroll
        for (int j = 0; j < TN; j++)
#pragma unroll
            for (int q = 0; q < 4; q++) c[i][j][q] = 0.f;

    for (int k0 = 0; k0 < 128; k0 += 32) {
#pragma unroll
        for (int it = 0; it < 4; it++) {
            int idx = tid + it * 256;
            int r = idx >> 3, cg = (idx & 7) * 4;
            int gr = row0 + r; if (gr >= NN) gr = 0;
            float4 v = __ldg((const float4*)(A + (size_t)gr * 128 + k0 + cg));
            *(uint4*)&As[r][cg] = make_uint4(f2tf(v.x), f2tf(v.y), f2tf(v.z), f2tf(v.w));
        }
        constexpr int WIT = (32 * BN) / (256 * 4);
#pragma unroll
        for (int it = 0; it < WIT; it++) {
            int idx = tid + it * 256;
            int n = idx % BN, g = idx / BN;
            uint32_t w0 = f2tf(__ldg(W + (size_t)(k0 + 4 * g + 0) * BN + n));
            uint32_t w1 = f2tf(__ldg(W + (size_t)(k0 + 4 * g + 1) * BN + n));
            uint32_t w2 = f2tf(__ldg(W + (size_t)(k0 + 4 * g + 2) * BN + n));
            uint32_t w3 = f2tf(__ldg(W + (size_t)(k0 + 4 * g + 3) * BN + n));
            *(uint4*)&Wt[n][4 * g] = make_uint4(w0, w1, w2, w3);
        }
        __syncthreads();

#pragma unroll
        for (int kk = 0; kk < 4; kk++) {
            const int ac = kk * 8 + (lane & 3);
            uint32_t a[2][4];
            const int ar = warp_m * 32 + (lane >> 2);
#pragma unroll
            for (int tm = 0; tm < 2; tm++) {
                a[tm][0] = As[ar + tm * 16][ac];
                a[tm][1] = As[ar + tm * 16 + 8][ac];
                a[tm][2] = As[ar + tm * 16][ac + 4];
                a[tm][3] = As[ar + tm * 16 + 8][ac + 4];
            }
#pragma unroll
            for (int tn = 0; tn < TN; tn++) {
                uint32_t b[2];
                int bn = warp_n * WN + tn * 8 + (lane >> 2);
                b[0] = Wt[bn][ac];
                b[1] = Wt[bn][ac + 4];
                mma_tf32(c[0][tn], a[0], b);
                mma_tf32(c[1][tn], a[1], b);
            }
        }
        __syncthreads();
    }

#pragma unroll
    for (int tm = 0; tm < 2; tm++) {
        int rbase = row0 + warp_m * 32 + tm * 16 + (lane >> 2);
#pragma unroll
        for (int half = 0; half < 2; half++) {
            int rr = rbase + half * 8;
            if (rr < NN) {
                float sc = SCALE ? __ldg(g_dinv + rr) : 1.f;
#pragma unroll
                for (int tn = 0; tn < TN; tn++) {
                    int n = warp_n * WN + tn * 8 + 2 * (lane & 3);
                    *(half2*)(C + (size_t)rr * BN + n) =
                        __floats2half2_rn(c[tm][tn][2 * half] * sc,
                                          c[tm][tn][2 * half + 1] * sc);
                }
            }
        }
    }
}

__global__ void __launch_bounds__(256) k_gemm1(const float* __restrict__ A,
                                               const float* __restrict__ W) {
    gemm_tf32_body<128, false>(A, W, g_h1);
}
__global__ void __launch_bounds__(256) k_gemm2(const float* __restrict__ W) {
    gemm_tf32_body<64, true>(g_agg, W, g_h2);
}

// ---------------- layer-1 aggregation: warp per node, fp16 gather, fused epilogue ----------------
// agg[d] = relu( (sum_s h1[s]*dinv[s] + h1[d]*dinv[d]) * dinv[d] + b1 ) * mask * 2
__device__ __forceinline__ void acc_h4(float4& ae, uint2 u, float w) {
    float2 f0 = __half22float2(*reinterpret_cast<half2*>(&u.x));
    float2 f1 = __half22float2(*reinterpret_cast<half2*>(&u.y));
    ae.x = fmaf(f0.x, w, ae.x); ae.y = fmaf(f0.y, w, ae.y);
    ae.z = fmaf(f1.x, w, ae.z); ae.w = fmaf(f1.y, w, ae.w);
}

__global__ void __launch_bounds__(256) k_agg1(const float* __restrict__ b1) {
    int d = (blockIdx.x * 256 + threadIdx.x) >> 5;
    if (d >= NN) return;
    int lane = threadIdx.x & 31;
    float dind = __ldg(g_dinv + d);

    const uint2* hb = (const uint2*)g_h1;   // 32 uint2 per row (128 halves)
    float4 ae = make_float4(0.f, 0.f, 0.f, 0.f);
    acc_h4(ae, __ldg(hb + (size_t)d * 32 + lane), dind);   // self term

    int beg = __ldg(g_off + d), end = __ldg(g_off + d + 1);
    int i = beg;
    for (; i + 4 <= end; i += 4) {
        int s0 = __ldg(g_srcs + i + 0);
        int s1 = __ldg(g_srcs + i + 1);
        int s2 = __ldg(g_srcs + i + 2);
        int s3 = __ldg(g_srcs + i + 3);
        float w0 = __ldg(g_sw + i + 0), w1 = __ldg(g_sw + i + 1);
        float w2 = __ldg(g_sw + i + 2), w3 = __ldg(g_sw + i + 3);
        uint2 u0 = __ldg(hb + (size_t)s0 * 32 + lane);
        uint2 u1 = __ldg(hb + (size_t)s1 * 32 + lane);
        uint2 u2 = __ldg(hb + (size_t)s2 * 32 + lane);
        uint2 u3 = __ldg(hb + (size_t)s3 * 32 + lane);
        acc_h4(ae, u0, w0); acc_h4(ae, u1, w1);
        acc_h4(ae, u2, w2); acc_h4(ae, u3, w3);
    }
    for (; i < end; i++) {
        int s = __ldg(g_srcs + i);
        float w = __ldg(g_sw + i);
        acc_h4(ae, __ldg(hb + (size_t)s * 32 + lane), w);
    }

    float4 acc = make_float4(ae.x * dind, ae.y * dind, ae.z * dind, ae.w * dind);

    int f = lane * 4;
    float4 bv = __ldg((const float4*)(b1 + f));
    unsigned m = g_mask[((size_t)d * 128 + f) >> 5];
    int bit = f & 31;
    acc.x = fmaxf(acc.x + bv.x, 0.f) * (((m >> (bit + 0)) & 1u) ? 2.f : 0.f);
    acc.y = fmaxf(acc.y + bv.y, 0.f) * (((m >> (bit + 1)) & 1u) ? 2.f : 0.f);
    acc.z = fmaxf(acc.z + bv.z, 0.f) * (((m >> (bit + 2)) & 1u) ? 2.f : 0.f);
    acc.w = fmaxf(acc.w + bv.w, 0.f) * (((m >> (bit + 3)) & 1u) ? 2.f : 0.f);
    *(float4*)(g_agg + (size_t)d * 128 + lane * 4) = acc;
}

// ---------------- layer-2 aggregation: half warp per node, fp16 gather (pre-scaled) ----------------
// out[d] = (sum_s h2s[s] + h2s[d]) * dinv[d] + b2
__global__ void __launch_bounds__(256) k_agg2(const float* __restrict__ b2,
                                              float* __restrict__ out) {
    int t = blockIdx.x * 256 + threadIdx.x;
    int d = t >> 4;
    if (d >= NN) return;
    int l = t & 15;
    float dind = __ldg(g_dinv + d);

    const uint2* hb = (const uint2*)g_h2;   // 16 uint2 per row (64 halves)
    float4 ae = make_float4(0.f, 0.f, 0.f, 0.f);
    acc_h4(ae, __ldg(hb + (size_t)d * 16 + l), 1.f);   // self term (pre-scaled)

    int beg = __ldg(g_off + d), end = __ldg(g_off + d + 1);
    int i = beg;
    for (; i + 4 <= end; i += 4) {
        int s0 = __ldg(g_srcs + i + 0);
        int s1 = __ldg(g_srcs + i + 1);
        int s2 = __ldg(g_srcs + i + 2);
        int s3 = __ldg(g_srcs + i + 3);
        uint2 u0 = __ldg(hb + (size_t)s0 * 16 + l);
        uint2 u1 = __ldg(hb + (size_t)s1 * 16 + l);
        uint2 u2 = __ldg(hb + (size_t)s2 * 16 + l);
        uint2 u3 = __ldg(hb + (size_t)s3 * 16 + l);
        acc_h4(ae, u0, 1.f); acc_h4(ae, u1, 1.f);
        acc_h4(ae, u2, 1.f); acc_h4(ae, u3, 1.f);
    }
    for (; i < end; i++) {
        int s = __ldg(g_srcs + i);
        acc_h4(ae, __ldg(hb + (size_t)s * 16 + l), 1.f);
    }

    float4 bv = __ldg((const float4*)(b2 + l * 4));
    float4 acc;
    acc.x = fmaf(ae.x, dind, bv.x);
    acc.y = fmaf(ae.y, dind, bv.y);
    acc.z = fmaf(ae.z, dind, bv.z);
    acc.w = fmaf(ae.w, dind, bv.w);
    *(float4*)(out + (size_t)d * 64 + l * 4) = acc;
}

// ---------------- launch: fork mask & GEMM1 onto side streams, join before agg1 ----------------
extern "C" void kernel_launch(void* const* d_in, const int* in_sizes, int n_in,
                              void* d_out, int out_size) {
    const float* x  = (const float*)d_in[0];
    const int*   ei = (const int*)d_in[1];
    const float* W1 = (const float*)d_in[2];
    const float* b1 = (const float*)d_in[3];
    const float* W2 = (const float*)d_in[4];
    const float* b2 = (const float*)d_in[5];
    const int* src = ei;
    const int* dst = ei + NE;
    float* out = (float*)d_out;

    static cudaStream_t sA = nullptr, sB = nullptr;
    static cudaEvent_t evRoot = nullptr, evA = nullptr, evB = nullptr;
    if (sA == nullptr) {
        cudaStreamCreateWithFlags(&sA, cudaStreamNonBlocking);
        cudaStreamCreateWithFlags(&sB, cudaStreamNonBlocking);
        cudaEventCreateWithFlags(&evRoot, cudaEventDisableTiming);
        cudaEventCreateWithFlags(&evA, cudaEventDisableTiming);
        cudaEventCreateWithFlags(&evB, cudaEventDisableTiming);
    }

    cudaEventRecord(evRoot, 0);
    cudaStreamWaitEvent(sA, evRoot, 0);
    cudaStreamWaitEvent(sB, evRoot, 0);

    // stream A: dropout mask
    k_mask<<<(NN * FH) / 256, 256, 0, sA>>>();
    cudaEventRecord(evA, sA);

    // stream B: GEMM1 (tensor cores, fp16 out)
    k_gemm1<<<(NN + 127) / 128, 256, 0, sB>>>(x, W1);
    cudaEventRecord(evB, sB);

    // default stream: CSR build
    k_deg_zero<<<NBLK, 256>>>();
    k_deg_count<<<(NE + 255) / 256, 256>>>(dst);
    k_blocksum<<<NBLK, 256>>>();
    k_scan_bsum<<<1, 512>>>();
    k_nodeoff<<<NBLK, 256>>>();
    k_fill<<<(NE + 255) / 256, 256>>>(src, dst);

    cudaStreamWaitEvent(0, evA, 0);
    cudaStreamWaitEvent(0, evB, 0);

    k_agg1<<<(NN * 32 + 255) / 256, 256>>>(b1);
    k_gemm2<<<(NN + 127) / 128, 256>>>(W2);
    k_agg2<<<(NN * 16 + 255) / 256, 256>>>(b2, out);
}

// round 7
// speedup vs baseline: 2.8604x; 1.1478x over previous
#include <cuda_runtime.h>
#include <cuda_fp16.h>
#include <cstdint>

#define NN 100000
#define NE 1600000
#define FH 128
#define FO 64
#define NBLK 391             // ceil(NN/256)

__device__ int      g_dege[NN];      // real in-degree (no self loop)
__device__ float    g_dinv[NN];
__device__ int      g_off[NN + 1];
__device__ int      g_cur[NN];
__device__ int2     g_edge[NE];      // {src, bitcast(dinv[src])} per CSR slot
__device__ int      g_bsum[NBLK];
__device__ int      g_boff[NBLK];
__device__ __half   g_h1[(size_t)NN * FH];   // fp16, unscaled
__device__ __half   g_agg[(size_t)NN * FH];  // fp16 (GEMM2 input, post relu+dropout)
__device__ __half   g_h2[(size_t)NN * FO];   // fp16, pre-scaled by dinv[row]

// ---------------- degree ----------------
__global__ void k_deg_zero() {
    int i = blockIdx.x * blockDim.x + threadIdx.x;
    if (i < NN) g_dege[i] = 0;
}
__global__ void k_deg_count(const int* __restrict__ dst) {
    int e = blockIdx.x * blockDim.x + threadIdx.x;
    if (e < NE) atomicAdd(&g_dege[dst[e]], 1);
}

// ---------------- CSR build: two-level exclusive scan ----------------
__global__ void __launch_bounds__(256) k_blocksum() {
    __shared__ int sh[8];
    int i = blockIdx.x * 256 + threadIdx.x;
    int v = (i < NN) ? g_dege[i] : 0;
#pragma unroll
    for (int o = 16; o > 0; o >>= 1) v += __shfl_down_sync(0xffffffffu, v, o);
    if ((threadIdx.x & 31) == 0) sh[threadIdx.x >> 5] = v;
    __syncthreads();
    if (threadIdx.x < 8) {
        int t = sh[threadIdx.x];
#pragma unroll
        for (int o = 4; o > 0; o >>= 1) t += __shfl_down_sync(0xffu, t, o);
        if (threadIdx.x == 0) g_bsum[blockIdx.x] = t;
    }
}

__global__ void __launch_bounds__(512) k_scan_bsum() {
    __shared__ int sh[512];
    int t = threadIdx.x;
    sh[t] = (t < NBLK) ? g_bsum[t] : 0;
    __syncthreads();
#pragma unroll
    for (int o = 1; o < 512; o <<= 1) {
        int v = (t >= o) ? sh[t - o] : 0;
        __syncthreads();
        sh[t] += v;
        __syncthreads();
    }
    if (t < NBLK) g_boff[t] = sh[t] - g_bsum[t];   // exclusive
}

__global__ void __launch_bounds__(256) k_nodeoff() {
    __shared__ int sh[256];
    int i = blockIdx.x * 256 + threadIdx.x;
    int t = threadIdx.x;
    int d = (i < NN) ? g_dege[i] : 0;
    sh[t] = d;
    __syncthreads();
#pragma unroll
    for (int o = 1; o < 256; o <<= 1) {
        int v = (t >= o) ? sh[t - o] : 0;
        __syncthreads();
        sh[t] += v;
        __syncthreads();
    }
    if (i < NN) {
        int off = g_boff[blockIdx.x] + sh[t] - d;   // exclusive
        g_off[i] = off;
        g_cur[i] = off;
        g_dinv[i] = rsqrtf((float)(d + 1));         // +1 self loop
        if (i == NN - 1) g_off[NN] = off + d;
    }
}

__global__ void k_fill(const int* __restrict__ src, const int* __restrict__ dst) {
    int e = blockIdx.x * blockDim.x + threadIdx.x;
    if (e >= NE) return;
    int s = src[e];
    int slot = atomicAdd(&g_cur[dst[e]], 1);
    g_edge[slot] = make_int2(s, __float_as_int(__ldg(g_dinv + s)));
}

// ---------------- JAX threefry2x32 (partitionable path) ----------------
__device__ __forceinline__ uint2 threefry2x32_0_42(unsigned x0, unsigned x1) {
    const unsigned ks0 = 0u, ks1 = 42u, ks2 = 0u ^ 42u ^ 0x1BD11BDAu;
    x0 += ks0; x1 += ks1;
#define TF_R(r) { x0 += x1; x1 = __funnelshift_l(x1, x1, (r)); x1 ^= x0; }
    TF_R(13) TF_R(15) TF_R(26) TF_R(6)
    x0 += ks1; x1 += ks2 + 1u;
    TF_R(17) TF_R(29) TF_R(16) TF_R(24)
    x0 += ks2; x1 += ks0 + 2u;
    TF_R(13) TF_R(15) TF_R(26) TF_R(6)
    x0 += ks0; x1 += ks1 + 3u;
    TF_R(17) TF_R(29) TF_R(16) TF_R(24)
    x0 += ks1; x1 += ks2 + 4u;
    TF_R(13) TF_R(15) TF_R(26) TF_R(6)
    x0 += ks2; x1 += ks0 + 5u;
#undef TF_R
    return make_uint2(x0, x1);
}
// keep(i) <=> bit31(out.x ^ out.y) == 0 for counter (0, i)
__device__ __forceinline__ float drop_mul(unsigned i) {
    uint2 o = threefry2x32_0_42(0u, i);
    return ((int)(o.x ^ o.y) >= 0) ? 2.f : 0.f;
}

// ---------------- fp16 tensor-core GEMM: C[NN x BN] = A[NN x 128] * W[128 x BN] ----------------
// A either fp32 (converted on load) or fp16. Output fp16 (optionally row-scaled by dinv).
__device__ __forceinline__ void mma_f16(float* c, const uint32_t* a, uint32_t b0, uint32_t b1) {
    asm volatile(
        "mma.sync.aligned.m16n8k16.row.col.f32.f16.f16.f32 "
        "{%0,%1,%2,%3}, {%4,%5,%6,%7}, {%8,%9}, {%0,%1,%2,%3};\n"
        : "+f"(c[0]), "+f"(c[1]), "+f"(c[2]), "+f"(c[3])
        : "r"(a[0]), "r"(a[1]), "r"(a[2]), "r"(a[3]), "r"(b0), "r"(b1));
}

template <int BN, bool A_HALF, bool SCALE>
__device__ __forceinline__ void gemm_f16_body(const void* __restrict__ Aptr,
                                              const float* __restrict__ W,
                                              __half* __restrict__ C) {
    __shared__ uint32_t As[128][36];   // half2 units: 32 k2 (=64 k) per stage + pad
    __shared__ uint32_t Wt[BN][36];    // [n][k2]
    const int tid = threadIdx.x;
    const int lane = tid & 31, wid = tid >> 5;
    const int warp_m = wid & 3, warp_n = wid >> 2;
    const int row0 = blockIdx.x * 128;
    constexpr int WN = BN / 2;
    constexpr int TN = WN / 8;

    float c[2][TN][4];
#pragma unroll
    for (int i = 0; i < 2; i++)
#pragma unroll
        for (int j = 0; j < TN; j++)
#pragma unroll
            for (int q = 0; q < 4; q++) c[i][j][q] = 0.f;

    for (int k0 = 0; k0 < 128; k0 += 64) {   // two stages of K=64
        // ---- stage A: 128 rows x 32 half2
        if (A_HALF) {
            const uint4* Ab = (const uint4*)Aptr;   // 16 uint4 per 128-half row
#pragma unroll
            for (int it = 0; it < 4; it++) {
                int idx = tid + it * 256;
                int r = idx >> 3, u = idx & 7;      // 8 uint4 per row-stage
                int gr = row0 + r; if (gr >= NN) gr = 0;
                uint4 v = __ldg(Ab + (size_t)gr * 16 + (k0 >> 3) + u);
                *(uint4*)&As[r][u * 4] = v;
            }
        } else {
            const float4* Af = (const float4*)Aptr; // 32 float4 per 128-float row
#pragma unroll
            for (int it = 0; it < 8; it++) {
                int idx = tid + it * 256;
                int r = idx >> 4, u = idx & 15;     // 16 float4 per row-stage
                int gr = row0 + r; if (gr >= NN) gr = 0;
                float4 v = __ldg(Af + (size_t)gr * 32 + (k0 >> 2) + u);
                half2 h0 = __floats2half2_rn(v.x, v.y);
                half2 h1 = __floats2half2_rn(v.z, v.w);
                As[r][u * 2 + 0] = *(uint32_t*)&h0;
                As[r][u * 2 + 1] = *(uint32_t*)&h1;
            }
        }
        // ---- stage W transposed: Wt[n][k2], 32 k2 x BN
        constexpr int WIT = (32 * BN) / 256;
#pragma unroll
        for (int it = 0; it < WIT; it++) {
            int idx = tid + it * 256;
            int n = idx % BN, k2 = idx / BN;        // k2 in 0..31
            half2 h = __floats2half2_rn(__ldg(W + (size_t)(k0 + 2 * k2) * BN + n),
                                        __ldg(W + (size_t)(k0 + 2 * k2 + 1) * BN + n));
            Wt[n][k2] = *(uint32_t*)&h;
        }
        __syncthreads();

#pragma unroll
        for (int kk = 0; kk < 4; kk++) {            // 4 x k16 per stage
            const int K2 = kk * 8;
            const int ar = warp_m * 32 + (lane >> 2);
            uint32_t a[2][4];
#pragma unroll
            for (int tm = 0; tm < 2; tm++) {
                a[tm][0] = As[ar + tm * 16][K2 + (lane & 3)];
                a[tm][1] = As[ar + tm * 16 + 8][K2 + (lane & 3)];
                a[tm][2] = As[ar + tm * 16][K2 + 4 + (lane & 3)];
                a[tm][3] = As[ar + tm * 16 + 8][K2 + 4 + (lane & 3)];
            }
#pragma unroll
            for (int tn = 0; tn < TN; tn++) {
                int bn = warp_n * WN + tn * 8 + (lane >> 2);
                uint32_t b0 = Wt[bn][K2 + (lane & 3)];
                uint32_t b1 = Wt[bn][K2 + 4 + (lane & 3)];
                mma_f16(c[0][tn], a[0], b0, b1);
                mma_f16(c[1][tn], a[1], b0, b1);
            }
        }
        __syncthreads();
    }

#pragma unroll
    for (int tm = 0; tm < 2; tm++) {
        int rbase = row0 + warp_m * 32 + tm * 16 + (lane >> 2);
#pragma unroll
        for (int half = 0; half < 2; half++) {
            int rr = rbase + half * 8;
            if (rr < NN) {
                float sc = SCALE ? __ldg(g_dinv + rr) : 1.f;
#pragma unroll
                for (int tn = 0; tn < TN; tn++) {
                    int n = warp_n * WN + tn * 8 + 2 * (lane & 3);
                    *(half2*)(C + (size_t)rr * BN + n) =
                        __floats2half2_rn(c[tm][tn][2 * half] * sc,
                                          c[tm][tn][2 * half + 1] * sc);
                }
            }
        }
    }
}

__global__ void __launch_bounds__(256) k_gemm1(const float* __restrict__ A,
                                               const float* __restrict__ W) {
    gemm_f16_body<128, false, false>(A, W, g_h1);
}
__global__ void __launch_bounds__(256) k_gemm2(const float* __restrict__ W) {
    gemm_f16_body<64, true, true>(g_agg, W, g_h2);
}

// ---------------- layer-1 aggregation: warp per node, fp16 gather, fused relu+dropout ----------------
__device__ __forceinline__ void acc_h4(float4& ae, uint2 u, float w) {
    float2 f0 = __half22float2(*reinterpret_cast<half2*>(&u.x));
    float2 f1 = __half22float2(*reinterpret_cast<half2*>(&u.y));
    ae.x = fmaf(f0.x, w, ae.x); ae.y = fmaf(f0.y, w, ae.y);
    ae.z = fmaf(f1.x, w, ae.z); ae.w = fmaf(f1.y, w, ae.w);
}

__global__ void __launch_bounds__(256) k_agg1(const float* __restrict__ b1) {
    int d = (blockIdx.x * 256 + threadIdx.x) >> 5;
    if (d >= NN) return;
    int lane = threadIdx.x & 31;
    float dind = __ldg(g_dinv + d);

    const uint2* hb = (const uint2*)g_h1;   // 32 uint2 per row (128 halves)
    float4 ae = make_float4(0.f, 0.f, 0.f, 0.f);
    acc_h4(ae, __ldg(hb + (size_t)d * 32 + lane), dind);   // self term

    int beg = __ldg(g_off + d), end = __ldg(g_off + d + 1);
    int i = beg;
    for (; i + 4 <= end; i += 4) {
        int2 e0 = __ldg(g_edge + i + 0);
        int2 e1 = __ldg(g_edge + i + 1);
        int2 e2 = __ldg(g_edge + i + 2);
        int2 e3 = __ldg(g_edge + i + 3);
        uint2 u0 = __ldg(hb + (size_t)e0.x * 32 + lane);
        uint2 u1 = __ldg(hb + (size_t)e1.x * 32 + lane);
        uint2 u2 = __ldg(hb + (size_t)e2.x * 32 + lane);
        uint2 u3 = __ldg(hb + (size_t)e3.x * 32 + lane);
        acc_h4(ae, u0, __int_as_float(e0.y));
        acc_h4(ae, u1, __int_as_float(e1.y));
        acc_h4(ae, u2, __int_as_float(e2.y));
        acc_h4(ae, u3, __int_as_float(e3.y));
    }
    for (; i < end; i++) {
        int2 e = __ldg(g_edge + i);
        acc_h4(ae, __ldg(hb + (size_t)e.x * 32 + lane), __int_as_float(e.y));
    }

    int f = lane * 4;
    float4 bv = __ldg((const float4*)(b1 + f));
    unsigned base = (unsigned)d * 128u + (unsigned)f;
    float m0 = drop_mul(base + 0), m1 = drop_mul(base + 1);
    float m2 = drop_mul(base + 2), m3 = drop_mul(base + 3);
    float4 acc;
    acc.x = fmaxf(fmaf(ae.x, dind, bv.x), 0.f) * m0;
    acc.y = fmaxf(fmaf(ae.y, dind, bv.y), 0.f) * m1;
    acc.z = fmaxf(fmaf(ae.z, dind, bv.z), 0.f) * m2;
    acc.w = fmaxf(fmaf(ae.w, dind, bv.w), 0.f) * m3;

    half2 h0 = __floats2half2_rn(acc.x, acc.y);
    half2 h1 = __floats2half2_rn(acc.z, acc.w);
    uint2 st = make_uint2(*(uint32_t*)&h0, *(uint32_t*)&h1);
    *(uint2*)(g_agg + (size_t)d * 128 + f) = st;
}

// ---------------- layer-2 aggregation: half warp per node, fp16 gather (pre-scaled) ----------------
__global__ void __launch_bounds__(256) k_agg2(const float* __restrict__ b2,
                                              float* __restrict__ out) {
    int t = blockIdx.x * 256 + threadIdx.x;
    int d = t >> 4;
    if (d >= NN) return;
    int l = t & 15;
    float dind = __ldg(g_dinv + d);

    const uint2* hb = (const uint2*)g_h2;   // 16 uint2 per row (64 halves)
    float4 ae = make_float4(0.f, 0.f, 0.f, 0.f);
    acc_h4(ae, __ldg(hb + (size_t)d * 16 + l), 1.f);   // self term (pre-scaled)

    int beg = __ldg(g_off + d), end = __ldg(g_off + d + 1);
    int i = beg;
    for (; i + 4 <= end; i += 4) {
        int2 e0 = __ldg(g_edge + i + 0);
        int2 e1 = __ldg(g_edge + i + 1);
        int2 e2 = __ldg(g_edge + i + 2);
        int2 e3 = __ldg(g_edge + i + 3);
        uint2 u0 = __ldg(hb + (size_t)e0.x * 16 + l);
        uint2 u1 = __ldg(hb + (size_t)e1.x * 16 + l);
        uint2 u2 = __ldg(hb + (size_t)e2.x * 16 + l);
        uint2 u3 = __ldg(hb + (size_t)e3.x * 16 + l);
        acc_h4(ae, u0, 1.f); acc_h4(ae, u1, 1.f);
        acc_h4(ae, u2, 1.f); acc_h4(ae, u3, 1.f);
    }
    for (; i < end; i++) {
        int2 e = __ldg(g_edge + i);
        acc_h4(ae, __ldg(hb + (size_t)e.x * 16 + l), 1.f);
    }

    float4 bv = __ldg((const float4*)(b2 + l * 4));
    float4 acc;
    acc.x = fmaf(ae.x, dind, bv.x);
    acc.y = fmaf(ae.y, dind, bv.y);
    acc.z = fmaf(ae.z, dind, bv.z);
    acc.w = fmaf(ae.w, dind, bv.w);
    *(float4*)(out + (size_t)d * 64 + l * 4) = acc;
}

// ---------------- launch: GEMM1 forked onto side stream, CSR on default ----------------
extern "C" void kernel_launch(void* const* d_in, const int* in_sizes, int n_in,
                              void* d_out, int out_size) {
    const float* x  = (const float*)d_in[0];
    const int*   ei = (const int*)d_in[1];
    const float* W1 = (const float*)d_in[2];
    const float* b1 = (const float*)d_in[3];
    const float* W2 = (const float*)d_in[4];
    const float* b2 = (const float*)d_in[5];
    const int* src = ei;
    const int* dst = ei + NE;
    float* out = (float*)d_out;

    static cudaStream_t sB = nullptr;
    static cudaEvent_t evRoot = nullptr, evB = nullptr;
    if (sB == nullptr) {
        cudaStreamCreateWithFlags(&sB, cudaStreamNonBlocking);
        cudaEventCreateWithFlags(&evRoot, cudaEventDisableTiming);
        cudaEventCreateWithFlags(&evB, cudaEventDisableTiming);
    }

    cudaEventRecord(evRoot, 0);
    cudaStreamWaitEvent(sB, evRoot, 0);

    // stream B: GEMM1 (fp16 tensor cores)
    k_gemm1<<<(NN + 127) / 128, 256, 0, sB>>>(x, W1);
    cudaEventRecord(evB, sB);

    // default stream: CSR build
    k_deg_zero<<<NBLK, 256>>>();
    k_deg_count<<<(NE + 255) / 256, 256>>>(dst);
    k_blocksum<<<NBLK, 256>>>();
    k_scan_bsum<<<1, 512>>>();
    k_nodeoff<<<NBLK, 256>>>();
    k_fill<<<(NE + 255) / 256, 256>>>(src, dst);

    cudaStreamWaitEvent(0, evB, 0);

    k_agg1<<<(NN * 32 + 255) / 256, 256>>>(b1);       // + relu + dropout (threefry fused)
    k_gemm2<<<(NN + 127) / 128, 256>>>(W2);
    k_agg2<<<(NN * 16 + 255) / 256, 256>>>(b2, out);
}

// round 8
// speedup vs baseline: 2.9465x; 1.0301x over previous
#include <cuda_runtime.h>
#include <cuda_fp16.h>
#include <cstdint>

#define NN 100000
#define NE 1600000
#define FH 128
#define FO 64
#define NBLK 391             // ceil(NN/256)

__device__ int      g_dege[NN];      // real in-degree (no self loop)
__device__ float    g_dinv[NN];
__device__ int      g_off[NN + 1];
__device__ int      g_cur[NN];
__device__ int2     g_edge[NE];      // {src, bitcast(dinv[src])} per CSR slot
__device__ unsigned long long g_stat[NBLK];  // decoupled-lookback state
__device__ __half   g_h1[(size_t)NN * FH];   // fp16, unscaled
__device__ __half   g_agg[(size_t)NN * FH];  // fp16 (GEMM2 input, post relu+dropout)
__device__ __half   g_h2[(size_t)NN * FO];   // fp16, pre-scaled by dinv[row]

// ---------------- zero (degrees + scan state) ----------------
__global__ void k_zero() {
    int i = blockIdx.x * blockDim.x + threadIdx.x;   // 25088 threads
    if (i < NN / 4) *(int4*)(g_dege + i * 4) = make_int4(0, 0, 0, 0);
    if (i < NBLK) g_stat[i] = 0ULL;
}

// ---------------- degree count: 4 edges per thread ----------------
__global__ void __launch_bounds__(256) k_deg_count(const int* __restrict__ dst) {
    int t = blockIdx.x * blockDim.x + threadIdx.x;   // NE/4 threads
    if (t >= NE / 4) return;
    int4 d = __ldg((const int4*)dst + t);
    atomicAdd(&g_dege[d.x], 1);
    atomicAdd(&g_dege[d.y], 1);
    atomicAdd(&g_dege[d.z], 1);
    atomicAdd(&g_dege[d.w], 1);
}

// ---------------- CSR offsets: single-kernel decoupled-lookback scan ----------------
__global__ void __launch_bounds__(256) k_csr_scan() {
    __shared__ int sh[256];
    __shared__ int exc_sh;
    const int b = blockIdx.x, t = threadIdx.x;
    const int i = b * 256 + t;
    int d = (i < NN) ? g_dege[i] : 0;

    // block-local inclusive scan
    sh[t] = d;
    __syncthreads();
#pragma unroll
    for (int o = 1; o < 256; o <<= 1) {
        int v = (t >= o) ? sh[t - o] : 0;
        __syncthreads();
        sh[t] += v;
        __syncthreads();
    }
    const unsigned blocksum = (unsigned)sh[255];

    // lookback (warp 0)
    if (b == 0) {
        if (t == 0) {
            atomicExch(&g_stat[0], (2ULL << 32) | blocksum);
            exc_sh = 0;
        }
    } else if (t < 32) {
        if (t == 0) atomicExch(&g_stat[b], (1ULL << 32) | blocksum);
        __syncwarp();
        unsigned running = 0;
        int base = b - 1;
        while (true) {
            int p = base - t;
            unsigned long long s;
            if (p >= 0) {
                const volatile unsigned long long* ps =
                    (const volatile unsigned long long*)(g_stat + p);
                do { s = *ps; } while ((unsigned)(s >> 32) == 0u);
            } else {
                s = (2ULL << 32);   // virtual prefix 0 before block 0
            }
            unsigned ballot = __ballot_sync(0xffffffffu, (unsigned)(s >> 32) == 2u);
            unsigned val = (unsigned)s;
            unsigned contrib;
            bool done = (ballot != 0);
            if (done) {
                int firstp = __ffs(ballot) - 1;          // closest inclusive-prefix
                contrib = (t <= firstp) ? val : 0u;      // aggregates + that prefix
            } else {
                contrib = val;                           // all 32 aggregates
            }
#pragma unroll
            for (int o = 16; o > 0; o >>= 1)
                contrib += __shfl_down_sync(0xffffffffu, contrib, o);
            if (t == 0) running += contrib;
            if (done) break;
            base -= 32;
        }
        if (t == 0) {
            atomicExch(&g_stat[b], (2ULL << 32) | (blocksum + running));
            exc_sh = (int)running;
        }
    }
    __syncthreads();

    if (i < NN) {
        int off = exc_sh + sh[t] - d;   // exclusive
        g_off[i] = off;
        g_cur[i] = off;
        g_dinv[i] = rsqrtf((float)(d + 1));   // +1 self loop
        if (i == NN - 1) g_off[NN] = off + d;
    }
}

// ---------------- fill: 4 edges per thread ----------------
__global__ void __launch_bounds__(256) k_fill(const int* __restrict__ src,
                                              const int* __restrict__ dst) {
    int t = blockIdx.x * blockDim.x + threadIdx.x;   // NE/4 threads
    if (t >= NE / 4) return;
    int4 s4 = __ldg((const int4*)src + t);
    int4 d4 = __ldg((const int4*)dst + t);
#pragma unroll
    for (int j = 0; j < 4; j++) {
        int s = (j == 0) ? s4.x : (j == 1) ? s4.y : (j == 2) ? s4.z : s4.w;
        int d = (j == 0) ? d4.x : (j == 1) ? d4.y : (j == 2) ? d4.z : d4.w;
        int slot = atomicAdd(&g_cur[d], 1);
        g_edge[slot] = make_int2(s, __float_as_int(__ldg(g_dinv + s)));
    }
}

// ---------------- JAX threefry2x32 (partitionable path) ----------------
__device__ __forceinline__ uint2 threefry2x32_0_42(unsigned x0, unsigned x1) {
    const unsigned ks0 = 0u, ks1 = 42u, ks2 = 0u ^ 42u ^ 0x1BD11BDAu;
    x0 += ks0; x1 += ks1;
#define TF_R(r) { x0 += x1; x1 = __funnelshift_l(x1, x1, (r)); x1 ^= x0; }
    TF_R(13) TF_R(15) TF_R(26) TF_R(6)
    x0 += ks1; x1 += ks2 + 1u;
    TF_R(17) TF_R(29) TF_R(16) TF_R(24)
    x0 += ks2; x1 += ks0 + 2u;
    TF_R(13) TF_R(15) TF_R(26) TF_R(6)
    x0 += ks0; x1 += ks1 + 3u;
    TF_R(17) TF_R(29) TF_R(16) TF_R(24)
    x0 += ks1; x1 += ks2 + 4u;
    TF_R(13) TF_R(15) TF_R(26) TF_R(6)
    x0 += ks2; x1 += ks0 + 5u;
#undef TF_R
    return make_uint2(x0, x1);
}
__device__ __forceinline__ float drop_mul(unsigned i) {
    uint2 o = threefry2x32_0_42(0u, i);
    return ((int)(o.x ^ o.y) >= 0) ? 2.f : 0.f;
}

// ---------------- fp16 tensor-core GEMM: C[NN x BN] = A[NN x 128] * W[128 x BN] ----------------
__device__ __forceinline__ void mma_f16(float* c, const uint32_t* a, uint32_t b0, uint32_t b1) {
    asm volatile(
        "mma.sync.aligned.m16n8k16.row.col.f32.f16.f16.f32 "
        "{%0,%1,%2,%3}, {%4,%5,%6,%7}, {%8,%9}, {%0,%1,%2,%3};\n"
        : "+f"(c[0]), "+f"(c[1]), "+f"(c[2]), "+f"(c[3])
        : "r"(a[0]), "r"(a[1]), "r"(a[2]), "r"(a[3]), "r"(b0), "r"(b1));
}

template <int BN, bool A_HALF, bool SCALE>
__device__ __forceinline__ void gemm_f16_body(const void* __restrict__ Aptr,
                                              const float* __restrict__ W,
                                              __half* __restrict__ C) {
    __shared__ uint32_t As[128][36];
    __shared__ uint32_t Wt[BN][36];
    const int tid = threadIdx.x;
    const int lane = tid & 31, wid = tid >> 5;
    const int warp_m = wid & 3, warp_n = wid >> 2;
    const int row0 = blockIdx.x * 128;
    constexpr int WN = BN / 2;
    constexpr int TN = WN / 8;

    float c[2][TN][4];
#pragma unroll
    for (int i = 0; i < 2; i++)
#pragma unroll
        for (int j = 0; j < TN; j++)
#pragma unroll
            for (int q = 0; q < 4; q++) c[i][j][q] = 0.f;

    for (int k0 = 0; k0 < 128; k0 += 64) {
        if (A_HALF) {
            const uint4* Ab = (const uint4*)Aptr;
#pragma unroll
            for (int it = 0; it < 4; it++) {
                int idx = tid + it * 256;
                int r = idx >> 3, u = idx & 7;
                int gr = row0 + r; if (gr >= NN) gr = 0;
                uint4 v = __ldg(Ab + (size_t)gr * 16 + (k0 >> 3) + u);
                *(uint4*)&As[r][u * 4] = v;
            }
        } else {
            const float4* Af = (const float4*)Aptr;
#pragma unroll
            for (int it = 0; it < 8; it++) {
                int idx = tid + it * 256;
                int r = idx >> 4, u = idx & 15;
                int gr = row0 + r; if (gr >= NN) gr = 0;
                float4 v = __ldg(Af + (size_t)gr * 32 + (k0 >> 2) + u);
                half2 h0 = __floats2half2_rn(v.x, v.y);
                half2 h1 = __floats2half2_rn(v.z, v.w);
                As[r][u * 2 + 0] = *(uint32_t*)&h0;
                As[r][u * 2 + 1] = *(uint32_t*)&h1;
            }
        }
        constexpr int WIT = (32 * BN) / 256;
#pragma unroll
        for (int it = 0; it < WIT; it++) {
            int idx = tid + it * 256;
            int n = idx % BN, k2 = idx / BN;
            half2 h = __floats2half2_rn(__ldg(W + (size_t)(k0 + 2 * k2) * BN + n),
                                        __ldg(W + (size_t)(k0 + 2 * k2 + 1) * BN + n));
            Wt[n][k2] = *(uint32_t*)&h;
        }
        __syncthreads();

#pragma unroll
        for (int kk = 0; kk < 4; kk++) {
            const int K2 = kk * 8;
            const int ar = warp_m * 32 + (lane >> 2);
            uint32_t a[2][4];
#pragma unroll
            for (int tm = 0; tm < 2; tm++) {
                a[tm][0] = As[ar + tm * 16][K2 + (lane & 3)];
                a[tm][1] = As[ar + tm * 16 + 8][K2 + (lane & 3)];
                a[tm][2] = As[ar + tm * 16][K2 + 4 + (lane & 3)];
                a[tm][3] = As[ar + tm * 16 + 8][K2 + 4 + (lane & 3)];
            }
#pragma unroll
            for (int tn = 0; tn < TN; tn++) {
                int bn = warp_n * WN + tn * 8 + (lane >> 2);
                uint32_t b0 = Wt[bn][K2 + (lane & 3)];
                uint32_t b1 = Wt[bn][K2 + 4 + (lane & 3)];
                mma_f16(c[0][tn], a[0], b0, b1);
                mma_f16(c[1][tn], a[1], b0, b1);
            }
        }
        __syncthreads();
    }

#pragma unroll
    for (int tm = 0; tm < 2; tm++) {
        int rbase = row0 + warp_m * 32 + tm * 16 + (lane >> 2);
#pragma unroll
        for (int half = 0; half < 2; half++) {
            int rr = rbase + half * 8;
            if (rr < NN) {
                float sc = SCALE ? __ldg(g_dinv + rr) : 1.f;
#pragma unroll
                for (int tn = 0; tn < TN; tn++) {
                    int n = warp_n * WN + tn * 8 + 2 * (lane & 3);
                    *(half2*)(C + (size_t)rr * BN + n) =
                        __floats2half2_rn(c[tm][tn][2 * half] * sc,
                                          c[tm][tn][2 * half + 1] * sc);
                }
            }
        }
    }
}

__global__ void __launch_bounds__(256) k_gemm1(const float* __restrict__ A,
                                               const float* __restrict__ W) {
    gemm_f16_body<128, false, false>(A, W, g_h1);
}
__global__ void __launch_bounds__(256) k_gemm2(const float* __restrict__ W) {
    gemm_f16_body<64, true, true>(g_agg, W, g_h2);
}

// ---------------- layer-1 aggregation: warp per node, fp16 gather, fused relu+dropout ----------------
__device__ __forceinline__ void acc_h4(float4& ae, uint2 u, float w) {
    float2 f0 = __half22float2(*reinterpret_cast<half2*>(&u.x));
    float2 f1 = __half22float2(*reinterpret_cast<half2*>(&u.y));
    ae.x = fmaf(f0.x, w, ae.x); ae.y = fmaf(f0.y, w, ae.y);
    ae.z = fmaf(f1.x, w, ae.z); ae.w = fmaf(f1.y, w, ae.w);
}

__global__ void __launch_bounds__(256) k_agg1(const float* __restrict__ b1) {
    int d = (blockIdx.x * 256 + threadIdx.x) >> 5;
    if (d >= NN) return;
    int lane = threadIdx.x & 31;
    float dind = __ldg(g_dinv + d);

    const uint2* hb = (const uint2*)g_h1;
    float4 ae = make_float4(0.f, 0.f, 0.f, 0.f);
    acc_h4(ae, __ldg(hb + (size_t)d * 32 + lane), dind);   // self term

    int beg = __ldg(g_off + d), end = __ldg(g_off + d + 1);
    int i = beg;
    for (; i + 4 <= end; i += 4) {
        int2 e0 = __ldg(g_edge + i + 0);
        int2 e1 = __ldg(g_edge + i + 1);
        int2 e2 = __ldg(g_edge + i + 2);
        int2 e3 = __ldg(g_edge + i + 3);
        uint2 u0 = __ldg(hb + (size_t)e0.x * 32 + lane);
        uint2 u1 = __ldg(hb + (size_t)e1.x * 32 + lane);
        uint2 u2 = __ldg(hb + (size_t)e2.x * 32 + lane);
        uint2 u3 = __ldg(hb + (size_t)e3.x * 32 + lane);
        acc_h4(ae, u0, __int_as_float(e0.y));
        acc_h4(ae, u1, __int_as_float(e1.y));
        acc_h4(ae, u2, __int_as_float(e2.y));
        acc_h4(ae, u3, __int_as_float(e3.y));
    }
    for (; i < end; i++) {
        int2 e = __ldg(g_edge + i);
        acc_h4(ae, __ldg(hb + (size_t)e.x * 32 + lane), __int_as_float(e.y));
    }

    int f = lane * 4;
    float4 bv = __ldg((const float4*)(b1 + f));
    unsigned base = (unsigned)d * 128u + (unsigned)f;
    float m0 = drop_mul(base + 0), m1 = drop_mul(base + 1);
    float m2 = drop_mul(base + 2), m3 = drop_mul(base + 3);
    float4 acc;
    acc.x = fmaxf(fmaf(ae.x, dind, bv.x), 0.f) * m0;
    acc.y = fmaxf(fmaf(ae.y, dind, bv.y), 0.f) * m1;
    acc.z = fmaxf(fmaf(ae.z, dind, bv.z), 0.f) * m2;
    acc.w = fmaxf(fmaf(ae.w, dind, bv.w), 0.f) * m3;

    half2 h0 = __floats2half2_rn(acc.x, acc.y);
    half2 h1 = __floats2half2_rn(acc.z, acc.w);
    uint2 st = make_uint2(*(uint32_t*)&h0, *(uint32_t*)&h1);
    *(uint2*)(g_agg + (size_t)d * 128 + f) = st;
}

// ---------------- layer-2 aggregation: half warp per node, fp16 gather (pre-scaled) ----------------
__global__ void __launch_bounds__(256) k_agg2(const float* __restrict__ b2,
                                              float* __restrict__ out) {
    int t = blockIdx.x * 256 + threadIdx.x;
    int d = t >> 4;
    if (d >= NN) return;
    int l = t & 15;
    float dind = __ldg(g_dinv + d);

    const uint2* hb = (const uint2*)g_h2;
    float4 ae = make_float4(0.f, 0.f, 0.f, 0.f);
    acc_h4(ae, __ldg(hb + (size_t)d * 16 + l), 1.f);   // self term (pre-scaled)

    int beg = __ldg(g_off + d), end = __ldg(g_off + d + 1);
    int i = beg;
    for (; i + 4 <= end; i += 4) {
        int2 e0 = __ldg(g_edge + i + 0);
        int2 e1 = __ldg(g_edge + i + 1);
        int2 e2 = __ldg(g_edge + i + 2);
        int2 e3 = __ldg(g_edge + i + 3);
        uint2 u0 = __ldg(hb + (size_t)e0.x * 16 + l);
        uint2 u1 = __ldg(hb + (size_t)e1.x * 16 + l);
        uint2 u2 = __ldg(hb + (size_t)e2.x * 16 + l);
        uint2 u3 = __ldg(hb + (size_t)e3.x * 16 + l);
        acc_h4(ae, u0, 1.f); acc_h4(ae, u1, 1.f);
        acc_h4(ae, u2, 1.f); acc_h4(ae, u3, 1.f);
    }
    for (; i < end; i++) {
        int2 e = __ldg(g_edge + i);
        acc_h4(ae, __ldg(hb + (size_t)e.x * 16 + l), 1.f);
    }

    float4 bv = __ldg((const float4*)(b2 + l * 4));
    float4 acc;
    acc.x = fmaf(ae.x, dind, bv.x);
    acc.y = fmaf(ae.y, dind, bv.y);
    acc.z = fmaf(ae.z, dind, bv.z);
    acc.w = fmaf(ae.w, dind, bv.w);
    *(float4*)(out + (size_t)d * 64 + l * 4) = acc;
}

// ---------------- launch ----------------
extern "C" void kernel_launch(void* const* d_in, const int* in_sizes, int n_in,
                              void* d_out, int out_size) {
    const float* x  = (const float*)d_in[0];
    const int*   ei = (const int*)d_in[1];
    const float* W1 = (const float*)d_in[2];
    const float* b1 = (const float*)d_in[3];
    const float* W2 = (const float*)d_in[4];
    const float* b2 = (const float*)d_in[5];
    const int* src = ei;
    const int* dst = ei + NE;
    float* out = (float*)d_out;

    static cudaStream_t sB = nullptr;
    static cudaEvent_t evRoot = nullptr, evB = nullptr;
    if (sB == nullptr) {
        cudaStreamCreateWithFlags(&sB, cudaStreamNonBlocking);
        cudaEventCreateWithFlags(&evRoot, cudaEventDisableTiming);
        cudaEventCreateWithFlags(&evB, cudaEventDisableTiming);
    }

    cudaEventRecord(evRoot, 0);
    cudaStreamWaitEvent(sB, evRoot, 0);

    // stream B: GEMM1 (fp16 tensor cores) — hidden under CSR build
    k_gemm1<<<(NN + 127) / 128, 256, 0, sB>>>(x, W1);
    cudaEventRecord(evB, sB);

    // default stream: CSR build (4 kernels)
    k_zero<<<98, 256>>>();
    k_deg_count<<<(NE / 4 + 255) / 256, 256>>>(dst);
    k_csr_scan<<<NBLK, 256>>>();
    k_fill<<<(NE / 4 + 255) / 256, 256>>>(src, dst);

    cudaStreamWaitEvent(0, evB, 0);

    k_agg1<<<(NN * 32 + 255) / 256, 256>>>(b1);       // + relu + dropout (threefry fused)
    k_gemm2<<<(NN + 127) / 128, 256>>>(W2);
    k_agg2<<<(NN * 16 + 255) / 256, 256>>>(b2, out);
}